// round 11
// baseline (speedup 1.0000x reference)
#include <cuda_runtime.h>
#include <cuda_bf16.h>
#include <cstdint>

#define NT    512
#define NGRID 2048
#define NXF   16
#define HID   64
#define DLY   4
#define NG    128
#define NTHR  256
#define TCH   9
#define CH    57
#define RS    144        // weight tile row stride (72 bf16)

#define WT    (64 * RS)
#define WIT   (16 * RS)
#define SM_WXH_H 0
#define SM_WXH_L (WT)
#define SM_WHH_H (2 * WT)
#define SM_WHH_L (3 * WT)
#define SM_WIN_H (4 * WT)
#define SM_WIN_L (4 * WT + WIT)
#define SM_BIN   (4 * WT + 2 * WIT)
#define SM_BH    (SM_BIN + 256)
#define SM_WOUT  (SM_BH + 256)
#define SM_TOTAL (SM_WOUT + 256)

__device__ __forceinline__ uint32_t smem_u32(const void* p) {
    uint32_t a;
    asm("{ .reg .u64 t; cvta.to.shared.u64 t, %1; cvt.u32.u64 %0, t; }" : "=r"(a) : "l"(p));
    return a;
}

// no "memory" clobber: smem is read-only after the prologue barrier
#define LDSM4T(r, addr) \
    asm volatile("ldmatrix.sync.aligned.m8n8.x4.trans.shared.b16 {%0,%1,%2,%3}, [%4];" \
        : "=r"((r)[0]), "=r"((r)[1]), "=r"((r)[2]), "=r"((r)[3]) : "r"(addr))
#define MMA4(d, a, b0_, b1_) \
    asm volatile("mma.sync.aligned.m16n8k16.row.col.f32.bf16.bf16.f32 " \
        "{%0,%1,%2,%3}, {%4,%5,%6,%7}, {%8,%9}, {%0,%1,%2,%3};" \
        : "+f"((d)[0]), "+f"((d)[1]), "+f"((d)[2]), "+f"((d)[3]) \
        : "r"((a)[0]), "r"((a)[1]), "r"((a)[2]), "r"((a)[3]), "r"(b0_), "r"(b1_))

__device__ __forceinline__ float fast_tanh(float v) {
    float e = __expf(2.0f * v);
    return 1.0f - __fdividef(2.0f, e + 1.0f);
}
__device__ __forceinline__ uint32_t packhi(float a, float b) {
    uint32_t r;
    asm("prmt.b32 %0, %1, %2, 0x7632;"
        : "=r"(r) : "r"(__float_as_uint(a)), "r"(__float_as_uint(b)));
    return r;
}
__device__ __forceinline__ uint32_t packlo(float a, float b) {
    float ha = __uint_as_float(__float_as_uint(a) & 0xFFFF0000u);
    float hb = __uint_as_float(__float_as_uint(b) & 0xFFFF0000u);
    __nv_bfloat162 t = __floats2bfloat162_rn(a - ha, b - hb);
    return *(uint32_t*)&t;
}

// tanh 4 values of n8-chunk j of SRC, pack to A-frag slots of (SHp,SLp). j literal.
#define SCHUNK(SRC, SHp, SLp, j) do { \
    float s0 = fast_tanh((SRC)[4*(j)+0]); \
    float s1 = fast_tanh((SRC)[4*(j)+1]); \
    float s2 = fast_tanh((SRC)[4*(j)+2]); \
    float s3 = fast_tanh((SRC)[4*(j)+3]); \
    if (((j) & 1) == 0) { \
        (SHp)[((j)>>1)*4+0] = packhi(s0, s1); (SLp)[((j)>>1)*4+0] = packlo(s0, s1); \
        (SHp)[((j)>>1)*4+1] = packhi(s2, s3); (SLp)[((j)>>1)*4+1] = packlo(s2, s3); \
    } else { \
        (SHp)[((j)>>1)*4+2] = packhi(s0, s1); (SLp)[((j)>>1)*4+2] = packlo(s0, s1); \
        (SHp)[((j)>>1)*4+3] = packhi(s2, s3); (SLp)[((j)>>1)*4+3] = packlo(s2, s3); \
    } \
} while (0)

#define YCHUNK(j) do { \
    float2 w2 = *(const float2*)&wop[(j) * 8 + 2 * c]; \
    p  += fast_tanh(G1[4*(j)+0]) * w2.x + fast_tanh(G1[4*(j)+1]) * w2.y; \
    p8 += fast_tanh(G1[4*(j)+2]) * w2.x + fast_tanh(G1[4*(j)+3]) * w2.y; \
} while (0)

#define UGEMM_CHUNK(ntp) do { \
    uint32_t b4[4], c4[4]; \
    LDSM4T(b4, win_h + (ntp) * 32); \
    LDSM4T(c4, win_l + (ntp) * 32); \
    MMA4(&uacc[(ntp)*8],   xh, b4[0], b4[1]); MMA4(&uacc[(ntp)*8+4], xh, b4[2], b4[3]); \
    MMA4(&uacc[(ntp)*8],   xl, b4[0], b4[1]); MMA4(&uacc[(ntp)*8+4], xl, b4[2], b4[3]); \
    MMA4(&uacc[(ntp)*8],   xh, c4[0], c4[1]); MMA4(&uacc[(ntp)*8+4], xh, c4[2], c4[3]); \
} while (0)

#define UPACK(j) do { \
    float u0 = fmaxf(uacc[4*(j)+0], 0.f); \
    float u1 = fmaxf(uacc[4*(j)+1], 0.f); \
    float u2 = fmaxf(uacc[4*(j)+2], 0.f); \
    float u3 = fmaxf(uacc[4*(j)+3], 0.f); \
    if (((j) & 1) == 0) { \
        uh[((j)>>1)*4+0] = packhi(u0, u1); ul[((j)>>1)*4+0] = packlo(u0, u1); \
        uh[((j)>>1)*4+1] = packhi(u2, u3); ul[((j)>>1)*4+1] = packlo(u2, u3); \
    } else { \
        uh[((j)>>1)*4+2] = packhi(u0, u1); ul[((j)>>1)*4+2] = packlo(u0, u1); \
        uh[((j)>>1)*4+3] = packhi(u2, u3); ul[((j)>>1)*4+3] = packlo(u2, u3); \
    } \
} while (0)

#define AGEMM_CHUNK(kt, ntp) do { \
    uint32_t b4[4], c4[4]; \
    LDSM4T(b4, wxh_h + (kt) * (16 * RS) + (ntp) * 32); \
    LDSM4T(c4, wxh_l + (kt) * (16 * RS) + (ntp) * 32); \
    MMA4(&An[(ntp)*8],   &uh[(kt)*4], b4[0], b4[1]); MMA4(&An[(ntp)*8+4], &uh[(kt)*4], b4[2], b4[3]); \
    MMA4(&An[(ntp)*8],   &ul[(kt)*4], b4[0], b4[1]); MMA4(&An[(ntp)*8+4], &ul[(kt)*4], b4[2], b4[3]); \
    MMA4(&An[(ntp)*8],   &uh[(kt)*4], c4[0], c4[1]); MMA4(&An[(ntp)*8+4], &uh[(kt)*4], c4[2], c4[3]); \
} while (0)

extern "C" __global__ void __launch_bounds__(NTHR, 1)
narx_frag_kernel(const float* __restrict__ x,
                 const float* __restrict__ W_in,  const float* __restrict__ b_in,
                 const float* __restrict__ W_xh,  const float* __restrict__ W_hh,
                 const float* __restrict__ b_h,   const float* __restrict__ W_out,
                 const float* __restrict__ b_out, float* __restrict__ out)
{
    __shared__ __align__(16) char smp[SM_TOTAL];
    const uint32_t sb = smem_u32(smp);
    const int tid = threadIdx.x, wid = tid >> 5, lane = tid & 31;
    const int gr = lane >> 2, c = lane & 3;
    const int m0 = wid * 16;
    const int cell0 = blockIdx.x * NG;
    const int tb = blockIdx.y * CH;
    const int te = min(tb + CH, NT - 1);
    const int ts = max(tb - (DLY - 1), 0);
    const int emit_lo = max(tb, DLY - 1);

    // ---- prologue: truncation-split weights into smem (hi/lo bf16) ----
    for (int i = tid; i < HID * HID; i += NTHR) {
        int k = i >> 6, n = i & 63;
        float w1 = W_xh[i];
        uint32_t h1 = __float_as_uint(w1) & 0xFFFF0000u;
        ((uint16_t*)(smp + SM_WXH_H))[k*72 + n] = (uint16_t)(h1 >> 16);
        ((__nv_bfloat16*)(smp + SM_WXH_L))[k*72 + n] = __float2bfloat16(w1 - __uint_as_float(h1));
        float w2 = W_hh[i];
        uint32_t h2 = __float_as_uint(w2) & 0xFFFF0000u;
        ((uint16_t*)(smp + SM_WHH_H))[k*72 + n] = (uint16_t)(h2 >> 16);
        ((__nv_bfloat16*)(smp + SM_WHH_L))[k*72 + n] = __float2bfloat16(w2 - __uint_as_float(h2));
    }
    for (int i = tid; i < NXF * HID; i += NTHR) {
        int k = i >> 6, n = i & 63;
        float w = W_in[i];
        uint32_t h = __float_as_uint(w) & 0xFFFF0000u;
        ((uint16_t*)(smp + SM_WIN_H))[k*72 + n] = (uint16_t)(h >> 16);
        ((__nv_bfloat16*)(smp + SM_WIN_L))[k*72 + n] = __float2bfloat16(w - __uint_as_float(h));
    }
    if (tid < HID) {
        ((float*)(smp + SM_BIN))[tid]  = b_in[tid];
        ((float*)(smp + SM_BH))[tid]   = b_h[tid];
        ((float*)(smp + SM_WOUT))[tid] = W_out[tid];
    }
    const float bout = b_out[0];
    __syncthreads();   // smem read-only hereafter

    const uint32_t bOff  = (uint32_t)(((lane & 7) + ((lane >> 3) & 1) * 8) * RS + (lane >> 4) * 16);
    const uint32_t wxh_h = sb + SM_WXH_H + bOff;
    const uint32_t wxh_l = sb + SM_WXH_L + bOff;
    const uint32_t whh_h = sb + SM_WHH_H + bOff;
    const uint32_t whh_l = sb + SM_WHH_L + bOff;
    const uint32_t win_h = sb + SM_WIN_H + bOff;
    const uint32_t win_l = sb + SM_WIN_L + bOff;

    const float* binp = (const float*)(smp + SM_BIN);
    const float* bhp  = (const float*)(smp + SM_BH);
    const float* wop  = (const float*)(smp + SM_WOUT);

    uint32_t SH[3][16], SL[3][16];
    #pragma unroll
    for (int r = 0; r < 3; ++r)
        #pragma unroll
        for (int q = 0; q < 16; ++q) { SH[r][q] = 0u; SL[r][q] = 0u; }

    const size_t tstride = (size_t)NGRID * NXF;
    const float* xr0 = x + ((size_t)ts * NGRID + cell0 + m0 + gr)     * NXF + 2 * c;
    const float* xr8 = x + ((size_t)ts * NGRID + cell0 + m0 + gr + 8) * NXF + 2 * c;

    float Acur[32];
    // ---- pre-loop: U(ts), Acur(ts) ----
    {
        float2 v0 = *(const float2*)(xr0);
        float2 v1 = *(const float2*)(xr0 + 8);
        float2 v2 = *(const float2*)(xr8);
        float2 v3 = *(const float2*)(xr8 + 8);
        uint32_t xh[4], xl[4];
        xh[0] = packhi(v0.x, v0.y); xl[0] = packlo(v0.x, v0.y);
        xh[1] = packhi(v2.x, v2.y); xl[1] = packlo(v2.x, v2.y);
        xh[2] = packhi(v1.x, v1.y); xl[2] = packlo(v1.x, v1.y);
        xh[3] = packhi(v3.x, v3.y); xl[3] = packlo(v3.x, v3.y);
        float uacc[32];
        #pragma unroll
        for (int j = 0; j < 8; ++j) {
            float2 b2 = *(const float2*)&binp[j * 8 + 2 * c];
            uacc[4*j+0] = b2.x; uacc[4*j+1] = b2.y; uacc[4*j+2] = b2.x; uacc[4*j+3] = b2.y;
        }
        UGEMM_CHUNK(0); UGEMM_CHUNK(1); UGEMM_CHUNK(2); UGEMM_CHUNK(3);
        uint32_t uh[16], ul[16];
        UPACK(0); UPACK(1); UPACK(2); UPACK(3); UPACK(4); UPACK(5); UPACK(6); UPACK(7);
        float An[32];
        #pragma unroll
        for (int j = 0; j < 8; ++j) {
            float2 b2 = *(const float2*)&bhp[j * 8 + 2 * c];
            An[4*j+0] = b2.x; An[4*j+1] = b2.y; An[4*j+2] = b2.x; An[4*j+3] = b2.y;
        }
        #pragma unroll
        for (int kt = 0; kt < 4; ++kt) {
            AGEMM_CHUNK(kt, 0); AGEMM_CHUNK(kt, 1); AGEMM_CHUNK(kt, 2); AGEMM_CHUNK(kt, 3);
        }
        #pragma unroll
        for (int i = 0; i < 32; ++i) Acur[i] = An[i];
    }
    xr0 += tstride; xr8 += tstride;   // now point at t+1 rows

    for (int t = ts; t < te; ++t) {
        // prefetch x(t+1) (consumed mid phase-2; latency hidden by state GEMM)
        float2 xn0 = *(const float2*)(xr0);
        float2 xn1 = *(const float2*)(xr0 + 8);
        float2 xn2 = *(const float2*)(xr8);
        float2 xn3 = *(const float2*)(xr8 + 8);
        xr0 += tstride; xr8 += tstride;

        // ---- phase 1: fused state GEMMs, accumulators seeded with A ----
        // G1 = A + S3old@W (-> y), G2 = A + S2old@W (-> S3new), G3 = A + S1old@W (-> S2new)
        float G1[32], G2[32], G3[32];
        #pragma unroll
        for (int i = 0; i < 32; ++i) { G1[i] = Acur[i]; G2[i] = Acur[i]; G3[i] = Acur[i]; }
        #pragma unroll
        for (int kt = 0; kt < 4; ++kt) {
            #pragma unroll
            for (int ntp = 0; ntp < 4; ++ntp) {
                uint32_t b4[4], c4[4];
                LDSM4T(b4, whh_h + kt * (16 * RS) + ntp * 32);
                LDSM4T(c4, whh_l + kt * (16 * RS) + ntp * 32);
                MMA4(&G1[ntp*8],   &SH[2][kt*4], b4[0], b4[1]); MMA4(&G1[ntp*8+4], &SH[2][kt*4], b4[2], b4[3]);
                MMA4(&G2[ntp*8],   &SH[1][kt*4], b4[0], b4[1]); MMA4(&G2[ntp*8+4], &SH[1][kt*4], b4[2], b4[3]);
                MMA4(&G3[ntp*8],   &SH[0][kt*4], b4[0], b4[1]); MMA4(&G3[ntp*8+4], &SH[0][kt*4], b4[2], b4[3]);
                MMA4(&G1[ntp*8],   &SL[2][kt*4], b4[0], b4[1]); MMA4(&G1[ntp*8+4], &SL[2][kt*4], b4[2], b4[3]);
                MMA4(&G2[ntp*8],   &SL[1][kt*4], b4[0], b4[1]); MMA4(&G2[ntp*8+4], &SL[1][kt*4], b4[2], b4[3]);
                MMA4(&G3[ntp*8],   &SL[0][kt*4], b4[0], b4[1]); MMA4(&G3[ntp*8+4], &SL[0][kt*4], b4[2], b4[3]);
                MMA4(&G1[ntp*8],   &SH[2][kt*4], c4[0], c4[1]); MMA4(&G1[ntp*8+4], &SH[2][kt*4], c4[2], c4[3]);
                MMA4(&G2[ntp*8],   &SH[1][kt*4], c4[0], c4[1]); MMA4(&G2[ntp*8+4], &SH[1][kt*4], c4[2], c4[3]);
                MMA4(&G3[ntp*8],   &SH[0][kt*4], c4[0], c4[1]); MMA4(&G3[ntp*8+4], &SH[0][kt*4], c4[2], c4[3]);
            }
        }

        // ---- phase 2: MUFU tanh chunks interleaved with U/A GEMMs of t+1 ----
        uint32_t xh[4], xl[4];
        xh[0] = packhi(xn0.x, xn0.y); xl[0] = packlo(xn0.x, xn0.y);
        xh[1] = packhi(xn2.x, xn2.y); xl[1] = packlo(xn2.x, xn2.y);
        xh[2] = packhi(xn1.x, xn1.y); xl[2] = packlo(xn1.x, xn1.y);
        xh[3] = packhi(xn3.x, xn3.y); xl[3] = packlo(xn3.x, xn3.y);

        float uacc[32];
        #pragma unroll
        for (int j = 0; j < 8; ++j) {
            float2 b2 = *(const float2*)&binp[j * 8 + 2 * c];
            uacc[4*j+0] = b2.x; uacc[4*j+1] = b2.y; uacc[4*j+2] = b2.x; uacc[4*j+3] = b2.y;
        }

        // 2a: S1new = tanh(Acur) interleaved with U-GEMM (A dies here)
        SCHUNK(Acur, SH[0], SL[0], 0);
        UGEMM_CHUNK(0);
        SCHUNK(Acur, SH[0], SL[0], 1);
        SCHUNK(Acur, SH[0], SL[0], 2);
        UGEMM_CHUNK(1);
        SCHUNK(Acur, SH[0], SL[0], 3);
        SCHUNK(Acur, SH[0], SL[0], 4);
        UGEMM_CHUNK(2);
        SCHUNK(Acur, SH[0], SL[0], 5);
        SCHUNK(Acur, SH[0], SL[0], 6);
        UGEMM_CHUNK(3);
        SCHUNK(Acur, SH[0], SL[0], 7);

        uint32_t uh[16], ul[16];
        UPACK(0); UPACK(1); UPACK(2); UPACK(3); UPACK(4); UPACK(5); UPACK(6); UPACK(7);

        float An[32];
        #pragma unroll
        for (int j = 0; j < 8; ++j) {
            float2 b2 = *(const float2*)&bhp[j * 8 + 2 * c];
            An[4*j+0] = b2.x; An[4*j+1] = b2.y; An[4*j+2] = b2.x; An[4*j+3] = b2.y;
        }

        // 2b: A-GEMM (16 chunks) interleaved with y (G1), S3new (G2), S2new (G3)
        float p = 0.f, p8 = 0.f;
        AGEMM_CHUNK(0, 0); YCHUNK(0);
        AGEMM_CHUNK(0, 1); YCHUNK(1); YCHUNK(2);
        AGEMM_CHUNK(0, 2); YCHUNK(3);
        AGEMM_CHUNK(0, 3); YCHUNK(4); YCHUNK(5);
        AGEMM_CHUNK(1, 0); YCHUNK(6);
        AGEMM_CHUNK(1, 1); YCHUNK(7); SCHUNK(G2, SH[2], SL[2], 0);
        AGEMM_CHUNK(1, 2); SCHUNK(G2, SH[2], SL[2], 1);
        AGEMM_CHUNK(1, 3); SCHUNK(G2, SH[2], SL[2], 2); SCHUNK(G2, SH[2], SL[2], 3);
        AGEMM_CHUNK(2, 0); SCHUNK(G2, SH[2], SL[2], 4);
        AGEMM_CHUNK(2, 1); SCHUNK(G2, SH[2], SL[2], 5); SCHUNK(G2, SH[2], SL[2], 6);
        AGEMM_CHUNK(2, 2); SCHUNK(G2, SH[2], SL[2], 7);
        AGEMM_CHUNK(2, 3); SCHUNK(G3, SH[1], SL[1], 0); SCHUNK(G3, SH[1], SL[1], 1);
        AGEMM_CHUNK(3, 0); SCHUNK(G3, SH[1], SL[1], 2);
        AGEMM_CHUNK(3, 1); SCHUNK(G3, SH[1], SL[1], 3); SCHUNK(G3, SH[1], SL[1], 4);
        AGEMM_CHUNK(3, 2); SCHUNK(G3, SH[1], SL[1], 5);
        AGEMM_CHUNK(3, 3); SCHUNK(G3, SH[1], SL[1], 6); SCHUNK(G3, SH[1], SL[1], 7);

        #pragma unroll
        for (int i = 0; i < 32; ++i) Acur[i] = An[i];

        // ---- emit y ----
        p  += __shfl_xor_sync(0xffffffffu, p, 1);
        p  += __shfl_xor_sync(0xffffffffu, p, 2);
        p8 += __shfl_xor_sync(0xffffffffu, p8, 1);
        p8 += __shfl_xor_sync(0xffffffffu, p8, 2);
        if (c == 0 && t >= emit_lo) {
            size_t base = (size_t)(t + 1) * NGRID + cell0 + m0;
            out[base + gr]     = p  + bout;
            out[base + gr + 8] = p8 + bout;
        }
    }
}

extern "C" __global__ void narx_zero_head(float* __restrict__ out) {
    int i = blockIdx.x * blockDim.x + threadIdx.x;
    if (i < DLY * NGRID) out[i] = 0.f;
}

extern "C" void kernel_launch(void* const* d_in, const int* in_sizes, int n_in,
                              void* d_out, int out_size) {
    const float* x     = (const float*)d_in[0];
    const float* W_in  = (const float*)d_in[1];
    const float* b_in  = (const float*)d_in[2];
    const float* W_xh  = (const float*)d_in[3];
    const float* W_hh  = (const float*)d_in[4];
    const float* b_h   = (const float*)d_in[5];
    const float* W_out = (const float*)d_in[6];
    const float* b_out = (const float*)d_in[7];
    float* out = (float*)d_out;

    narx_zero_head<<<(DLY * NGRID + 255) / 256, 256>>>(out);

    dim3 grid(NGRID / NG, TCH);
    narx_frag_kernel<<<grid, NTHR>>>(
        x, W_in, b_in, W_xh, W_hh, b_h, W_out, b_out, out);
}

// round 12
// speedup vs baseline: 1.7970x; 1.7970x over previous
#include <cuda_runtime.h>
#include <cuda_fp16.h>
#include <cstdint>

#define NT    512
#define NGRID 2048
#define NXF   16
#define HID   64
#define DLY   4
#define NG    128
#define NTHR  256
#define TCH   9
#define CH    57
#define RS    144        // weight tile row stride (72 fp16)

#define WT    (64 * RS)
#define WIT   (16 * RS)
#define SM_WXH  0
#define SM_WHH  (WT)
#define SM_WIN  (2 * WT)
#define SM_BIN  (2 * WT + WIT)
#define SM_BH   (SM_BIN + 256)
#define SM_WOUT (SM_BH + 256)
#define SM_TOTAL (SM_WOUT + 256)   // ~21.5 KB

__device__ __forceinline__ uint32_t smem_u32(const void* p) {
    uint32_t a;
    asm("{ .reg .u64 t; cvta.to.shared.u64 t, %1; cvt.u32.u64 %0, t; }" : "=r"(a) : "l"(p));
    return a;
}

// no "memory" clobber: smem is read-only after the prologue barrier
#define LDSM4T(r, addr) \
    asm volatile("ldmatrix.sync.aligned.m8n8.x4.trans.shared.b16 {%0,%1,%2,%3}, [%4];" \
        : "=r"((r)[0]), "=r"((r)[1]), "=r"((r)[2]), "=r"((r)[3]) : "r"(addr))
#define MMA4(d, a, b0_, b1_) \
    asm volatile("mma.sync.aligned.m16n8k16.row.col.f32.f16.f16.f32 " \
        "{%0,%1,%2,%3}, {%4,%5,%6,%7}, {%8,%9}, {%0,%1,%2,%3};" \
        : "+f"((d)[0]), "+f"((d)[1]), "+f"((d)[2]), "+f"((d)[3]) \
        : "r"((a)[0]), "r"((a)[1]), "r"((a)[2]), "r"((a)[3]), "r"(b0_), "r"(b1_))

__device__ __forceinline__ float fast_tanh(float v) {
    float e = __expf(2.0f * v);
    return 1.0f - __fdividef(2.0f, e + 1.0f);
}
// hi = rn fp16x2 of (a,b)
__device__ __forceinline__ uint32_t packh2(float a, float b) {
    __half2 h = __floats2half2_rn(a, b);
    return *(uint32_t*)&h;
}
// lo = rn fp16x2 of residual (a,b) - hi
__device__ __forceinline__ uint32_t packl2(float a, float b, uint32_t hi) {
    __half2 h = *(__half2*)&hi;
    float2 f = __half22float2(h);
    __half2 l = __floats2half2_rn(a - f.x, b - f.y);
    return *(uint32_t*)&l;
}

extern "C" __global__ void __launch_bounds__(NTHR, 1)
narx_frag_kernel(const float* __restrict__ x,
                 const float* __restrict__ W_in,  const float* __restrict__ b_in,
                 const float* __restrict__ W_xh,  const float* __restrict__ W_hh,
                 const float* __restrict__ b_h,   const float* __restrict__ W_out,
                 const float* __restrict__ b_out, float* __restrict__ out)
{
    __shared__ __align__(16) char smp[SM_TOTAL];
    const uint32_t sb = smem_u32(smp);
    const int tid = threadIdx.x, wid = tid >> 5, lane = tid & 31;
    const int gr = lane >> 2, c = lane & 3;
    const int m0 = wid * 16;
    const int cell0 = blockIdx.x * NG;
    const int tb = blockIdx.y * CH;
    const int te = min(tb + CH, NT - 1);
    const int ts = max(tb - (DLY - 1), 0);
    const int emit_lo = max(tb, DLY - 1);

    // ---- prologue: fp16-rn weights into smem (hi only; 2-term scheme) ----
    for (int i = tid; i < HID * HID; i += NTHR) {
        int k = i >> 6, n = i & 63;
        ((__half*)(smp + SM_WXH))[k*72 + n] = __float2half_rn(W_xh[i]);
        ((__half*)(smp + SM_WHH))[k*72 + n] = __float2half_rn(W_hh[i]);
    }
    for (int i = tid; i < NXF * HID; i += NTHR) {
        int k = i >> 6, n = i & 63;
        ((__half*)(smp + SM_WIN))[k*72 + n] = __float2half_rn(W_in[i]);
    }
    if (tid < HID) {
        ((float*)(smp + SM_BIN))[tid]  = b_in[tid];
        ((float*)(smp + SM_BH))[tid]   = b_h[tid];
        ((float*)(smp + SM_WOUT))[tid] = W_out[tid];
    }
    const float bout = b_out[0];
    __syncthreads();   // smem read-only hereafter

    const uint32_t bOff = (uint32_t)(((lane & 7) + ((lane >> 3) & 1) * 8) * RS + (lane >> 4) * 16);
    const uint32_t wxh_b = sb + SM_WXH + bOff;
    const uint32_t whh_b = sb + SM_WHH + bOff;
    const uint32_t win_b = sb + SM_WIN + bOff;

    const float* binp = (const float*)(smp + SM_BIN);
    const float* bhp  = (const float*)(smp + SM_BH);
    const float* wop  = (const float*)(smp + SM_WOUT);

    // state A-frags in registers: 3 states x (4kt x 4regs) hi+lo, start at 0
    uint32_t SH[3][16], SL[3][16];
    #pragma unroll
    for (int r = 0; r < 3; ++r)
        #pragma unroll
        for (int q = 0; q < 16; ++q) { SH[r][q] = 0u; SL[r][q] = 0u; }

    const size_t tstride = (size_t)NGRID * NXF;
    const float* xr0 = x + ((size_t)ts * NGRID + cell0 + m0 + gr)     * NXF + 2 * c;
    const float* xr8 = x + ((size_t)ts * NGRID + cell0 + m0 + gr + 8) * NXF + 2 * c;
    float2 xn0 = *(const float2*)(xr0);
    float2 xn1 = *(const float2*)(xr0 + 8);
    float2 xn2 = *(const float2*)(xr8);
    float2 xn3 = *(const float2*)(xr8 + 8);
    xr0 += tstride; xr8 += tstride;

    for (int t = ts; t < te; ++t) {
        // ---- x A-frags (hi + residual fp16) ----
        uint32_t xh[4], xl[4];
        xh[0] = packh2(xn0.x, xn0.y); xl[0] = packl2(xn0.x, xn0.y, xh[0]);
        xh[1] = packh2(xn2.x, xn2.y); xl[1] = packl2(xn2.x, xn2.y, xh[1]);
        xh[2] = packh2(xn1.x, xn1.y); xl[2] = packl2(xn1.x, xn1.y, xh[2]);
        xh[3] = packh2(xn3.x, xn3.y); xl[3] = packl2(xn3.x, xn3.y, xh[3]);
        xn0 = *(const float2*)(xr0);
        xn1 = *(const float2*)(xr0 + 8);
        xn2 = *(const float2*)(xr8);
        xn3 = *(const float2*)(xr8 + 8);
        xr0 += tstride; xr8 += tstride;

        // ---- U = relu(x @ W_in + b_in), K=16, 2-term ----
        uint32_t uh[16], ul[16];
        {
            float acc[32];
            #pragma unroll
            for (int i = 0; i < 32; ++i) acc[i] = 0.f;
            #pragma unroll
            for (int ntp = 0; ntp < 4; ++ntp) {
                uint32_t b4[4];
                LDSM4T(b4, win_b + ntp * 32);
                MMA4(&acc[ntp*8],   xh, b4[0], b4[1]); MMA4(&acc[ntp*8+4], xh, b4[2], b4[3]);
                MMA4(&acc[ntp*8],   xl, b4[0], b4[1]); MMA4(&acc[ntp*8+4], xl, b4[2], b4[3]);
            }
            #pragma unroll
            for (int j = 0; j < 8; ++j) {
                float2 b2 = *(const float2*)&binp[j * 8 + 2 * c];
                float u0 = fmaxf(acc[4*j+0] + b2.x, 0.f);
                float u1 = fmaxf(acc[4*j+1] + b2.y, 0.f);
                float u2 = fmaxf(acc[4*j+2] + b2.x, 0.f);
                float u3 = fmaxf(acc[4*j+3] + b2.y, 0.f);
                const int kt = j >> 1;
                if ((j & 1) == 0) {
                    uh[kt*4+0] = packh2(u0, u1); ul[kt*4+0] = packl2(u0, u1, uh[kt*4+0]);
                    uh[kt*4+1] = packh2(u2, u3); ul[kt*4+1] = packl2(u2, u3, uh[kt*4+1]);
                } else {
                    uh[kt*4+2] = packh2(u0, u1); ul[kt*4+2] = packl2(u0, u1, uh[kt*4+2]);
                    uh[kt*4+3] = packh2(u2, u3); ul[kt*4+3] = packl2(u2, u3, uh[kt*4+3]);
                }
            }
        }

        // ---- A = U @ Wxh + b_h, K=64, 2-term ----
        float A[32];
        #pragma unroll
        for (int i = 0; i < 32; ++i) A[i] = 0.f;
        #pragma unroll
        for (int kt = 0; kt < 4; ++kt) {
            #pragma unroll
            for (int ntp = 0; ntp < 4; ++ntp) {
                uint32_t b4[4];
                LDSM4T(b4, wxh_b + kt * (16 * RS) + ntp * 32);
                MMA4(&A[ntp*8],   &uh[kt*4], b4[0], b4[1]); MMA4(&A[ntp*8+4], &uh[kt*4], b4[2], b4[3]);
                MMA4(&A[ntp*8],   &ul[kt*4], b4[0], b4[1]); MMA4(&A[ntp*8+4], &ul[kt*4], b4[2], b4[3]);
            }
        }
        #pragma unroll
        for (int j = 0; j < 8; ++j) {
            float2 b2 = *(const float2*)&bhp[j * 8 + 2 * c];
            A[4*j+0] += b2.x; A[4*j+1] += b2.y; A[4*j+2] += b2.x; A[4*j+3] += b2.y;
        }

        // ---- FUSED state GEMMs: G1=S3old@W, G2=S2old@W, G3=S1old@W (2-term) ----
        float G1[32], G2[32], G3[32];
        #pragma unroll
        for (int i = 0; i < 32; ++i) { G1[i] = 0.f; G2[i] = 0.f; G3[i] = 0.f; }
        #pragma unroll
        for (int kt = 0; kt < 4; ++kt) {
            #pragma unroll
            for (int ntp = 0; ntp < 4; ++ntp) {
                uint32_t b4[4];
                LDSM4T(b4, whh_b + kt * (16 * RS) + ntp * 32);
                MMA4(&G1[ntp*8],   &SH[2][kt*4], b4[0], b4[1]); MMA4(&G1[ntp*8+4], &SH[2][kt*4], b4[2], b4[3]);
                MMA4(&G2[ntp*8],   &SH[1][kt*4], b4[0], b4[1]); MMA4(&G2[ntp*8+4], &SH[1][kt*4], b4[2], b4[3]);
                MMA4(&G3[ntp*8],   &SH[0][kt*4], b4[0], b4[1]); MMA4(&G3[ntp*8+4], &SH[0][kt*4], b4[2], b4[3]);
                MMA4(&G1[ntp*8],   &SL[2][kt*4], b4[0], b4[1]); MMA4(&G1[ntp*8+4], &SL[2][kt*4], b4[2], b4[3]);
                MMA4(&G2[ntp*8],   &SL[1][kt*4], b4[0], b4[1]); MMA4(&G2[ntp*8+4], &SL[1][kt*4], b4[2], b4[3]);
                MMA4(&G3[ntp*8],   &SL[0][kt*4], b4[0], b4[1]); MMA4(&G3[ntp*8+4], &SL[0][kt*4], b4[2], b4[3]);
            }
        }

        // ---- epilogue: y from G1; S3new=tanh(A+G2); S2new=tanh(A+G3); S1new=tanh(A) ----
        float p = 0.f, p8 = 0.f;
        #pragma unroll
        for (int j = 0; j < 8; ++j) {
            float2 w2 = *(const float2*)&wop[j * 8 + 2 * c];
            p  += fast_tanh(A[4*j+0] + G1[4*j+0]) * w2.x
                + fast_tanh(A[4*j+1] + G1[4*j+1]) * w2.y;
            p8 += fast_tanh(A[4*j+2] + G1[4*j+2]) * w2.x
                + fast_tanh(A[4*j+3] + G1[4*j+3]) * w2.y;
        }
        #pragma unroll
        for (int j = 0; j < 8; ++j) {
            float s0 = fast_tanh(A[4*j+0] + G2[4*j+0]);
            float s1 = fast_tanh(A[4*j+1] + G2[4*j+1]);
            float s2 = fast_tanh(A[4*j+2] + G2[4*j+2]);
            float s3 = fast_tanh(A[4*j+3] + G2[4*j+3]);
            const int kt = j >> 1;
            if ((j & 1) == 0) {
                SH[2][kt*4+0] = packh2(s0, s1); SL[2][kt*4+0] = packl2(s0, s1, SH[2][kt*4+0]);
                SH[2][kt*4+1] = packh2(s2, s3); SL[2][kt*4+1] = packl2(s2, s3, SH[2][kt*4+1]);
            } else {
                SH[2][kt*4+2] = packh2(s0, s1); SL[2][kt*4+2] = packl2(s0, s1, SH[2][kt*4+2]);
                SH[2][kt*4+3] = packh2(s2, s3); SL[2][kt*4+3] = packl2(s2, s3, SH[2][kt*4+3]);
            }
        }
        #pragma unroll
        for (int j = 0; j < 8; ++j) {
            float s0 = fast_tanh(A[4*j+0] + G3[4*j+0]);
            float s1 = fast_tanh(A[4*j+1] + G3[4*j+1]);
            float s2 = fast_tanh(A[4*j+2] + G3[4*j+2]);
            float s3 = fast_tanh(A[4*j+3] + G3[4*j+3]);
            const int kt = j >> 1;
            if ((j & 1) == 0) {
                SH[1][kt*4+0] = packh2(s0, s1); SL[1][kt*4+0] = packl2(s0, s1, SH[1][kt*4+0]);
                SH[1][kt*4+1] = packh2(s2, s3); SL[1][kt*4+1] = packl2(s2, s3, SH[1][kt*4+1]);
            } else {
                SH[1][kt*4+2] = packh2(s0, s1); SL[1][kt*4+2] = packl2(s0, s1, SH[1][kt*4+2]);
                SH[1][kt*4+3] = packh2(s2, s3); SL[1][kt*4+3] = packl2(s2, s3, SH[1][kt*4+3]);
            }
        }
        #pragma unroll
        for (int j = 0; j < 8; ++j) {
            float s0 = fast_tanh(A[4*j+0]);
            float s1 = fast_tanh(A[4*j+1]);
            float s2 = fast_tanh(A[4*j+2]);
            float s3 = fast_tanh(A[4*j+3]);
            const int kt = j >> 1;
            if ((j & 1) == 0) {
                SH[0][kt*4+0] = packh2(s0, s1); SL[0][kt*4+0] = packl2(s0, s1, SH[0][kt*4+0]);
                SH[0][kt*4+1] = packh2(s2, s3); SL[0][kt*4+1] = packl2(s2, s3, SH[0][kt*4+1]);
            } else {
                SH[0][kt*4+2] = packh2(s0, s1); SL[0][kt*4+2] = packl2(s0, s1, SH[0][kt*4+2]);
                SH[0][kt*4+3] = packh2(s2, s3); SL[0][kt*4+3] = packl2(s2, s3, SH[0][kt*4+3]);
            }
        }

        // ---- emit y ----
        p  += __shfl_xor_sync(0xffffffffu, p, 1);
        p  += __shfl_xor_sync(0xffffffffu, p, 2);
        p8 += __shfl_xor_sync(0xffffffffu, p8, 1);
        p8 += __shfl_xor_sync(0xffffffffu, p8, 2);
        if (c == 0 && t >= emit_lo) {
            size_t base = (size_t)(t + 1) * NGRID + cell0 + m0;
            out[base + gr]     = p  + bout;
            out[base + gr + 8] = p8 + bout;
        }
    }
}

extern "C" __global__ void narx_zero_head(float* __restrict__ out) {
    int i = blockIdx.x * blockDim.x + threadIdx.x;
    if (i < DLY * NGRID) out[i] = 0.f;
}

extern "C" void kernel_launch(void* const* d_in, const int* in_sizes, int n_in,
                              void* d_out, int out_size) {
    const float* x     = (const float*)d_in[0];
    const float* W_in  = (const float*)d_in[1];
    const float* b_in  = (const float*)d_in[2];
    const float* W_xh  = (const float*)d_in[3];
    const float* W_hh  = (const float*)d_in[4];
    const float* b_h   = (const float*)d_in[5];
    const float* W_out = (const float*)d_in[6];
    const float* b_out = (const float*)d_in[7];
    float* out = (float*)d_out;

    narx_zero_head<<<(DLY * NGRID + 255) / 256, 256>>>(out);

    dim3 grid(NGRID / NG, TCH);
    narx_frag_kernel<<<grid, NTHR>>>(
        x, W_in, b_in, W_xh, W_hh, b_h, W_out, b_out, out);
}

// round 13
// speedup vs baseline: 2.1768x; 1.2114x over previous
#include <cuda_runtime.h>
#include <cuda_fp16.h>
#include <cstdint>

#define NT    512
#define NGRID 2048
#define NXF   16
#define HID   64
#define DLY   4
#define NG    128
#define NTHR  256
#define TCH   9
#define CH    57
#define RS    144        // weight tile row stride (72 fp16)

#define WT    (64 * RS)
#define WIT   (16 * RS)
#define SM_WXH  0
#define SM_WHH  (WT)
#define SM_WIN  (2 * WT)
#define SM_BIN  (2 * WT + WIT)
#define SM_BH   (SM_BIN + 256)
#define SM_WOUT (SM_BH + 256)
#define SM_TOTAL (SM_WOUT + 256)   // ~21.5 KB

__device__ __forceinline__ uint32_t smem_u32(const void* p) {
    uint32_t a;
    asm("{ .reg .u64 t; cvta.to.shared.u64 t, %1; cvt.u32.u64 %0, t; }" : "=r"(a) : "l"(p));
    return a;
}

// no "memory" clobber: smem is read-only after the prologue barrier
#define LDSM4T(r, addr) \
    asm volatile("ldmatrix.sync.aligned.m8n8.x4.trans.shared.b16 {%0,%1,%2,%3}, [%4];" \
        : "=r"((r)[0]), "=r"((r)[1]), "=r"((r)[2]), "=r"((r)[3]) : "r"(addr))
#define MMA4(d, a, b0_, b1_) \
    asm volatile("mma.sync.aligned.m16n8k16.row.col.f32.f16.f16.f32 " \
        "{%0,%1,%2,%3}, {%4,%5,%6,%7}, {%8,%9}, {%0,%1,%2,%3};" \
        : "+f"((d)[0]), "+f"((d)[1]), "+f"((d)[2]), "+f"((d)[3]) \
        : "r"((a)[0]), "r"((a)[1]), "r"((a)[2]), "r"((a)[3]), "r"(b0_), "r"(b1_))

__device__ __forceinline__ float fast_tanh(float v) {
    float e = __expf(2.0f * v);
    return 1.0f - __fdividef(2.0f, e + 1.0f);
}
__device__ __forceinline__ uint32_t packh2(float a, float b) {
    __half2 h = __floats2half2_rn(a, b);
    return *(uint32_t*)&h;
}
__device__ __forceinline__ uint32_t packl2(float a, float b, uint32_t hi) {
    __half2 h = *(__half2*)&hi;
    float2 f = __half22float2(h);
    __half2 l = __floats2half2_rn(a - f.x, b - f.y);
    return *(uint32_t*)&l;
}

extern "C" __global__ void __launch_bounds__(NTHR, 1)
narx_frag_kernel(const float* __restrict__ x,
                 const float* __restrict__ W_in,  const float* __restrict__ b_in,
                 const float* __restrict__ W_xh,  const float* __restrict__ W_hh,
                 const float* __restrict__ b_h,   const float* __restrict__ W_out,
                 const float* __restrict__ b_out, float* __restrict__ out)
{
    __shared__ __align__(16) char smp[SM_TOTAL];
    const uint32_t sb = smem_u32(smp);
    const int tid = threadIdx.x, wid = tid >> 5, lane = tid & 31;
    const int gr = lane >> 2, c = lane & 3;
    const int m0 = wid * 16;
    const int cell0 = blockIdx.x * NG;
    const int tb = blockIdx.y * CH;
    const int te = min(tb + CH, NT - 1);
    const int ts = max(tb - (DLY - 1), 0);
    const int emit_lo = max(tb, DLY - 1);

    // ---- prologue: fp16-rn weights into smem ----
    for (int i = tid; i < HID * HID; i += NTHR) {
        int k = i >> 6, n = i & 63;
        ((__half*)(smp + SM_WXH))[k*72 + n] = __float2half_rn(W_xh[i]);
        ((__half*)(smp + SM_WHH))[k*72 + n] = __float2half_rn(W_hh[i]);
    }
    for (int i = tid; i < NXF * HID; i += NTHR) {
        int k = i >> 6, n = i & 63;
        ((__half*)(smp + SM_WIN))[k*72 + n] = __float2half_rn(W_in[i]);
    }
    if (tid < HID) {
        ((float*)(smp + SM_BIN))[tid]  = b_in[tid];
        ((float*)(smp + SM_BH))[tid]   = b_h[tid];
        ((float*)(smp + SM_WOUT))[tid] = W_out[tid];
    }
    const float bout = b_out[0];
    __syncthreads();   // smem read-only hereafter

    const uint32_t bOff = (uint32_t)(((lane & 7) + ((lane >> 3) & 1) * 8) * RS + (lane >> 4) * 16);
    const uint32_t wxh_b = sb + SM_WXH + bOff;
    const uint32_t whh_b = sb + SM_WHH + bOff;
    const uint32_t win_b = sb + SM_WIN + bOff;

    const float* binp = (const float*)(smp + SM_BIN);
    const float* bhp  = (const float*)(smp + SM_BH);
    const float* wop  = (const float*)(smp + SM_WOUT);

    // state A-frags in registers: 3 states x (4kt x 4regs), fp16 hi only
    // (states are in (-1,1); fp16-rn carries ~2.4e-4 rel — the lo residual
    //  would be re-quantized next step anyway)
    uint32_t SH[3][16];
    #pragma unroll
    for (int r = 0; r < 3; ++r)
        #pragma unroll
        for (int q = 0; q < 16; ++q) SH[r][q] = 0u;

    const size_t tstride = (size_t)NGRID * NXF;
    const float* xr0 = x + ((size_t)ts * NGRID + cell0 + m0 + gr)     * NXF + 2 * c;
    const float* xr8 = x + ((size_t)ts * NGRID + cell0 + m0 + gr + 8) * NXF + 2 * c;
    float2 xn0 = *(const float2*)(xr0);
    float2 xn1 = *(const float2*)(xr0 + 8);
    float2 xn2 = *(const float2*)(xr8);
    float2 xn3 = *(const float2*)(xr8 + 8);
    xr0 += tstride; xr8 += tstride;

    for (int t = ts; t < te; ++t) {
        // ---- x A-frags (hi + residual fp16; x is unbounded, keep 2-term) ----
        uint32_t xh[4], xl[4];
        xh[0] = packh2(xn0.x, xn0.y); xl[0] = packl2(xn0.x, xn0.y, xh[0]);
        xh[1] = packh2(xn2.x, xn2.y); xl[1] = packl2(xn2.x, xn2.y, xh[1]);
        xh[2] = packh2(xn1.x, xn1.y); xl[2] = packl2(xn1.x, xn1.y, xh[2]);
        xh[3] = packh2(xn3.x, xn3.y); xl[3] = packl2(xn3.x, xn3.y, xh[3]);
        xn0 = *(const float2*)(xr0);
        xn1 = *(const float2*)(xr0 + 8);
        xn2 = *(const float2*)(xr8);
        xn3 = *(const float2*)(xr8 + 8);
        xr0 += tstride; xr8 += tstride;

        // ---- U = relu(x @ W_in + b_in), K=16, 2-term ----
        uint32_t uh[16], ul[16];
        {
            float acc[32];
            #pragma unroll
            for (int i = 0; i < 32; ++i) acc[i] = 0.f;
            #pragma unroll
            for (int ntp = 0; ntp < 4; ++ntp) {
                uint32_t b4[4];
                LDSM4T(b4, win_b + ntp * 32);
                MMA4(&acc[ntp*8],   xh, b4[0], b4[1]); MMA4(&acc[ntp*8+4], xh, b4[2], b4[3]);
                MMA4(&acc[ntp*8],   xl, b4[0], b4[1]); MMA4(&acc[ntp*8+4], xl, b4[2], b4[3]);
            }
            #pragma unroll
            for (int j = 0; j < 8; ++j) {
                float2 b2 = *(const float2*)&binp[j * 8 + 2 * c];
                float u0 = fmaxf(acc[4*j+0] + b2.x, 0.f);
                float u1 = fmaxf(acc[4*j+1] + b2.y, 0.f);
                float u2 = fmaxf(acc[4*j+2] + b2.x, 0.f);
                float u3 = fmaxf(acc[4*j+3] + b2.y, 0.f);
                const int kt = j >> 1;
                if ((j & 1) == 0) {
                    uh[kt*4+0] = packh2(u0, u1); ul[kt*4+0] = packl2(u0, u1, uh[kt*4+0]);
                    uh[kt*4+1] = packh2(u2, u3); ul[kt*4+1] = packl2(u2, u3, uh[kt*4+1]);
                } else {
                    uh[kt*4+2] = packh2(u0, u1); ul[kt*4+2] = packl2(u0, u1, uh[kt*4+2]);
                    uh[kt*4+3] = packh2(u2, u3); ul[kt*4+3] = packl2(u2, u3, uh[kt*4+3]);
                }
            }
        }

        // ---- A = U @ Wxh + b_h, K=64, 2-term ----
        float A[32];
        #pragma unroll
        for (int i = 0; i < 32; ++i) A[i] = 0.f;
        #pragma unroll
        for (int kt = 0; kt < 4; ++kt) {
            #pragma unroll
            for (int ntp = 0; ntp < 4; ++ntp) {
                uint32_t b4[4];
                LDSM4T(b4, wxh_b + kt * (16 * RS) + ntp * 32);
                MMA4(&A[ntp*8],   &uh[kt*4], b4[0], b4[1]); MMA4(&A[ntp*8+4], &uh[kt*4], b4[2], b4[3]);
                MMA4(&A[ntp*8],   &ul[kt*4], b4[0], b4[1]); MMA4(&A[ntp*8+4], &ul[kt*4], b4[2], b4[3]);
            }
        }
        #pragma unroll
        for (int j = 0; j < 8; ++j) {
            float2 b2 = *(const float2*)&bhp[j * 8 + 2 * c];
            A[4*j+0] += b2.x; A[4*j+1] += b2.y; A[4*j+2] += b2.x; A[4*j+3] += b2.y;
        }

        // ---- FUSED state GEMMs (hi-only): G1=S3old@W, G2=S2old@W, G3=S1old@W ----
        float G1[32], G2[32], G3[32];
        #pragma unroll
        for (int i = 0; i < 32; ++i) { G1[i] = 0.f; G2[i] = 0.f; G3[i] = 0.f; }
        #pragma unroll
        for (int kt = 0; kt < 4; ++kt) {
            #pragma unroll
            for (int ntp = 0; ntp < 4; ++ntp) {
                uint32_t b4[4];
                LDSM4T(b4, whh_b + kt * (16 * RS) + ntp * 32);
                MMA4(&G1[ntp*8],   &SH[2][kt*4], b4[0], b4[1]); MMA4(&G1[ntp*8+4], &SH[2][kt*4], b4[2], b4[3]);
                MMA4(&G2[ntp*8],   &SH[1][kt*4], b4[0], b4[1]); MMA4(&G2[ntp*8+4], &SH[1][kt*4], b4[2], b4[3]);
                MMA4(&G3[ntp*8],   &SH[0][kt*4], b4[0], b4[1]); MMA4(&G3[ntp*8+4], &SH[0][kt*4], b4[2], b4[3]);
            }
        }

        // ---- epilogue: y from G1; S3new=tanh(A+G2); S2new=tanh(A+G3); S1new=tanh(A) ----
        float p = 0.f, p8 = 0.f;
        #pragma unroll
        for (int j = 0; j < 8; ++j) {
            float2 w2 = *(const float2*)&wop[j * 8 + 2 * c];
            p  += fast_tanh(A[4*j+0] + G1[4*j+0]) * w2.x
                + fast_tanh(A[4*j+1] + G1[4*j+1]) * w2.y;
            p8 += fast_tanh(A[4*j+2] + G1[4*j+2]) * w2.x
                + fast_tanh(A[4*j+3] + G1[4*j+3]) * w2.y;
        }
        #pragma unroll
        for (int j = 0; j < 8; ++j) {
            float s0 = fast_tanh(A[4*j+0] + G2[4*j+0]);
            float s1 = fast_tanh(A[4*j+1] + G2[4*j+1]);
            float s2 = fast_tanh(A[4*j+2] + G2[4*j+2]);
            float s3 = fast_tanh(A[4*j+3] + G2[4*j+3]);
            const int kt = j >> 1;
            if ((j & 1) == 0) {
                SH[2][kt*4+0] = packh2(s0, s1);
                SH[2][kt*4+1] = packh2(s2, s3);
            } else {
                SH[2][kt*4+2] = packh2(s0, s1);
                SH[2][kt*4+3] = packh2(s2, s3);
            }
        }
        #pragma unroll
        for (int j = 0; j < 8; ++j) {
            float s0 = fast_tanh(A[4*j+0] + G3[4*j+0]);
            float s1 = fast_tanh(A[4*j+1] + G3[4*j+1]);
            float s2 = fast_tanh(A[4*j+2] + G3[4*j+2]);
            float s3 = fast_tanh(A[4*j+3] + G3[4*j+3]);
            const int kt = j >> 1;
            if ((j & 1) == 0) {
                SH[1][kt*4+0] = packh2(s0, s1);
                SH[1][kt*4+1] = packh2(s2, s3);
            } else {
                SH[1][kt*4+2] = packh2(s0, s1);
                SH[1][kt*4+3] = packh2(s2, s3);
            }
        }
        #pragma unroll
        for (int j = 0; j < 8; ++j) {
            float s0 = fast_tanh(A[4*j+0]);
            float s1 = fast_tanh(A[4*j+1]);
            float s2 = fast_tanh(A[4*j+2]);
            float s3 = fast_tanh(A[4*j+3]);
            const int kt = j >> 1;
            if ((j & 1) == 0) {
                SH[0][kt*4+0] = packh2(s0, s1);
                SH[0][kt*4+1] = packh2(s2, s3);
            } else {
                SH[0][kt*4+2] = packh2(s0, s1);
                SH[0][kt*4+3] = packh2(s2, s3);
            }
        }

        // ---- emit y ----
        p  += __shfl_xor_sync(0xffffffffu, p, 1);
        p  += __shfl_xor_sync(0xffffffffu, p, 2);
        p8 += __shfl_xor_sync(0xffffffffu, p8, 1);
        p8 += __shfl_xor_sync(0xffffffffu, p8, 2);
        if (c == 0 && t >= emit_lo) {
            size_t base = (size_t)(t + 1) * NGRID + cell0 + m0;
            out[base + gr]     = p  + bout;
            out[base + gr + 8] = p8 + bout;
        }
    }
}

extern "C" __global__ void narx_zero_head(float* __restrict__ out) {
    int i = blockIdx.x * blockDim.x + threadIdx.x;
    if (i < DLY * NGRID) out[i] = 0.f;
}

extern "C" void kernel_launch(void* const* d_in, const int* in_sizes, int n_in,
                              void* d_out, int out_size) {
    const float* x     = (const float*)d_in[0];
    const float* W_in  = (const float*)d_in[1];
    const float* b_in  = (const float*)d_in[2];
    const float* W_xh  = (const float*)d_in[3];
    const float* W_hh  = (const float*)d_in[4];
    const float* b_h   = (const float*)d_in[5];
    const float* W_out = (const float*)d_in[6];
    const float* b_out = (const float*)d_in[7];
    float* out = (float*)d_out;

    narx_zero_head<<<(DLY * NGRID + 255) / 256, 256>>>(out);

    dim3 grid(NGRID / NG, TCH);
    narx_frag_kernel<<<grid, NTHR>>>(
        x, W_in, b_in, W_xh, W_hh, b_h, W_out, b_out, out);
}

// round 14
// speedup vs baseline: 2.2946x; 1.0541x over previous
#include <cuda_runtime.h>
#include <cuda_fp16.h>
#include <cstdint>

#define NT    512
#define NGRID 2048
#define NXF   16
#define HID   64
#define DLY   4
#define NG    128
#define NTHR  256
#define TCH   9
#define CH    57
#define RS    144        // weight tile row stride (72 fp16)

#define WT    (64 * RS)
#define WIT   (16 * RS)
#define SM_WXH  0
#define SM_WHH  (WT)
#define SM_WIN  (2 * WT)
#define SM_BIN  (2 * WT + WIT)
#define SM_BH   (SM_BIN + 256)
#define SM_WOUT (SM_BH + 256)
#define SM_TOTAL (SM_WOUT + 256)   // ~21.5 KB

__device__ __forceinline__ uint32_t smem_u32(const void* p) {
    uint32_t a;
    asm("{ .reg .u64 t; cvta.to.shared.u64 t, %1; cvt.u32.u64 %0, t; }" : "=r"(a) : "l"(p));
    return a;
}

// no "memory" clobber: smem is read-only after the prologue barrier
#define LDSM4T(r, addr) \
    asm volatile("ldmatrix.sync.aligned.m8n8.x4.trans.shared.b16 {%0,%1,%2,%3}, [%4];" \
        : "=r"((r)[0]), "=r"((r)[1]), "=r"((r)[2]), "=r"((r)[3]) : "r"(addr))
#define MMA4(d, a, b0_, b1_) \
    asm volatile("mma.sync.aligned.m16n8k16.row.col.f32.f16.f16.f32 " \
        "{%0,%1,%2,%3}, {%4,%5,%6,%7}, {%8,%9}, {%0,%1,%2,%3};" \
        : "+f"((d)[0]), "+f"((d)[1]), "+f"((d)[2]), "+f"((d)[3]) \
        : "r"((a)[0]), "r"((a)[1]), "r"((a)[2]), "r"((a)[3]), "r"(b0_), "r"(b1_))

// 4 tanh sharing ONE reciprocal: tanh(v) = 1 - 2/(e^{2v}+1).
// d_i = min(e^{2v_i}+1, 1e7) (saturation keeps products finite; err <= 2e-7).
// r = rcp(d0 d1 d2 d3); 1/d_i recovered by multiplies. 5 MUFU per 4 tanh.
__device__ __forceinline__ void tanh4(float v0, float v1, float v2, float v3,
                                      float& s0, float& s1, float& s2, float& s3) {
    float d0 = fminf(__expf(2.f * v0) + 1.f, 1e7f);
    float d1 = fminf(__expf(2.f * v1) + 1.f, 1e7f);
    float d2 = fminf(__expf(2.f * v2) + 1.f, 1e7f);
    float d3 = fminf(__expf(2.f * v3) + 1.f, 1e7f);
    float p01 = d0 * d1, p23 = d2 * d3;
    float P = p01 * p23;
    float r;
    asm("rcp.approx.f32 %0, %1;" : "=f"(r) : "f"(P));
    float r01 = r * p23;   // 1/(d0*d1)
    float r23 = r * p01;   // 1/(d2*d3)
    s0 = fmaf(-2.f, d1 * r01, 1.f);
    s1 = fmaf(-2.f, d0 * r01, 1.f);
    s2 = fmaf(-2.f, d3 * r23, 1.f);
    s3 = fmaf(-2.f, d2 * r23, 1.f);
}

__device__ __forceinline__ uint32_t packh2(float a, float b) {
    __half2 h = __floats2half2_rn(a, b);
    return *(uint32_t*)&h;
}
__device__ __forceinline__ uint32_t packl2(float a, float b, uint32_t hi) {
    __half2 h = *(__half2*)&hi;
    float2 f = __half22float2(h);
    __half2 l = __floats2half2_rn(a - f.x, b - f.y);
    return *(uint32_t*)&l;
}

extern "C" __global__ void __launch_bounds__(NTHR, 1)
narx_frag_kernel(const float* __restrict__ x,
                 const float* __restrict__ W_in,  const float* __restrict__ b_in,
                 const float* __restrict__ W_xh,  const float* __restrict__ W_hh,
                 const float* __restrict__ b_h,   const float* __restrict__ W_out,
                 const float* __restrict__ b_out, float* __restrict__ out)
{
    __shared__ __align__(16) char smp[SM_TOTAL];
    const uint32_t sb = smem_u32(smp);
    const int tid = threadIdx.x, wid = tid >> 5, lane = tid & 31;
    const int gr = lane >> 2, c = lane & 3;
    const int m0 = wid * 16;
    const int cell0 = blockIdx.x * NG;
    const int tb = blockIdx.y * CH;
    const int te = min(tb + CH, NT - 1);
    const int ts = max(tb - (DLY - 1), 0);
    const int emit_lo = max(tb, DLY - 1);

    // ---- prologue: fp16-rn weights into smem ----
    for (int i = tid; i < HID * HID; i += NTHR) {
        int k = i >> 6, n = i & 63;
        ((__half*)(smp + SM_WXH))[k*72 + n] = __float2half_rn(W_xh[i]);
        ((__half*)(smp + SM_WHH))[k*72 + n] = __float2half_rn(W_hh[i]);
    }
    for (int i = tid; i < NXF * HID; i += NTHR) {
        int k = i >> 6, n = i & 63;
        ((__half*)(smp + SM_WIN))[k*72 + n] = __float2half_rn(W_in[i]);
    }
    if (tid < HID) {
        ((float*)(smp + SM_BIN))[tid]  = b_in[tid];
        ((float*)(smp + SM_BH))[tid]   = b_h[tid];
        ((float*)(smp + SM_WOUT))[tid] = W_out[tid];
    }
    const float bout = b_out[0];
    __syncthreads();   // smem read-only hereafter

    const uint32_t bOff = (uint32_t)(((lane & 7) + ((lane >> 3) & 1) * 8) * RS + (lane >> 4) * 16);
    const uint32_t wxh_b = sb + SM_WXH + bOff;
    const uint32_t whh_b = sb + SM_WHH + bOff;
    const uint32_t win_b = sb + SM_WIN + bOff;

    const float* binp = (const float*)(smp + SM_BIN);
    const float* bhp  = (const float*)(smp + SM_BH);
    const float* wop  = (const float*)(smp + SM_WOUT);

    // state A-frags in registers: 3 states x (4kt x 4regs), fp16 hi only
    uint32_t SH[3][16];
    #pragma unroll
    for (int r = 0; r < 3; ++r)
        #pragma unroll
        for (int q = 0; q < 16; ++q) SH[r][q] = 0u;

    const size_t tstride = (size_t)NGRID * NXF;
    const float* xr0 = x + ((size_t)ts * NGRID + cell0 + m0 + gr)     * NXF + 2 * c;
    const float* xr8 = x + ((size_t)ts * NGRID + cell0 + m0 + gr + 8) * NXF + 2 * c;
    float2 xn0 = *(const float2*)(xr0);
    float2 xn1 = *(const float2*)(xr0 + 8);
    float2 xn2 = *(const float2*)(xr8);
    float2 xn3 = *(const float2*)(xr8 + 8);
    xr0 += tstride; xr8 += tstride;

    for (int t = ts; t < te; ++t) {
        // ---- x A-frags (hi + residual fp16; x unbounded, keep 2-term) ----
        uint32_t xh[4], xl[4];
        xh[0] = packh2(xn0.x, xn0.y); xl[0] = packl2(xn0.x, xn0.y, xh[0]);
        xh[1] = packh2(xn2.x, xn2.y); xl[1] = packl2(xn2.x, xn2.y, xh[1]);
        xh[2] = packh2(xn1.x, xn1.y); xl[2] = packl2(xn1.x, xn1.y, xh[2]);
        xh[3] = packh2(xn3.x, xn3.y); xl[3] = packl2(xn3.x, xn3.y, xh[3]);
        xn0 = *(const float2*)(xr0);
        xn1 = *(const float2*)(xr0 + 8);
        xn2 = *(const float2*)(xr8);
        xn3 = *(const float2*)(xr8 + 8);
        xr0 += tstride; xr8 += tstride;

        // ---- U = relu(x @ W_in + b_in), K=16, 2-term in x ----
        uint32_t uh[16];
        {
            float acc[32];
            #pragma unroll
            for (int i = 0; i < 32; ++i) acc[i] = 0.f;
            #pragma unroll
            for (int ntp = 0; ntp < 4; ++ntp) {
                uint32_t b4[4];
                LDSM4T(b4, win_b + ntp * 32);
                MMA4(&acc[ntp*8],   xh, b4[0], b4[1]); MMA4(&acc[ntp*8+4], xh, b4[2], b4[3]);
                MMA4(&acc[ntp*8],   xl, b4[0], b4[1]); MMA4(&acc[ntp*8+4], xl, b4[2], b4[3]);
            }
            #pragma unroll
            for (int j = 0; j < 8; ++j) {
                float2 b2 = *(const float2*)&binp[j * 8 + 2 * c];
                float u0 = fmaxf(acc[4*j+0] + b2.x, 0.f);
                float u1 = fmaxf(acc[4*j+1] + b2.y, 0.f);
                float u2 = fmaxf(acc[4*j+2] + b2.x, 0.f);
                float u3 = fmaxf(acc[4*j+3] + b2.y, 0.f);
                const int kt = j >> 1;
                if ((j & 1) == 0) {
                    uh[kt*4+0] = packh2(u0, u1);
                    uh[kt*4+1] = packh2(u2, u3);
                } else {
                    uh[kt*4+2] = packh2(u0, u1);
                    uh[kt*4+3] = packh2(u2, u3);
                }
            }
        }

        // ---- A = U @ Wxh + b_h, K=64 (hi-only U) ----
        float A[32];
        #pragma unroll
        for (int i = 0; i < 32; ++i) A[i] = 0.f;
        #pragma unroll
        for (int kt = 0; kt < 4; ++kt) {
            #pragma unroll
            for (int ntp = 0; ntp < 4; ++ntp) {
                uint32_t b4[4];
                LDSM4T(b4, wxh_b + kt * (16 * RS) + ntp * 32);
                MMA4(&A[ntp*8],   &uh[kt*4], b4[0], b4[1]); MMA4(&A[ntp*8+4], &uh[kt*4], b4[2], b4[3]);
            }
        }
        #pragma unroll
        for (int j = 0; j < 8; ++j) {
            float2 b2 = *(const float2*)&bhp[j * 8 + 2 * c];
            A[4*j+0] += b2.x; A[4*j+1] += b2.y; A[4*j+2] += b2.x; A[4*j+3] += b2.y;
        }

        // ---- FUSED state GEMMs (hi-only): G1=S3old@W, G2=S2old@W, G3=S1old@W ----
        float G1[32], G2[32], G3[32];
        #pragma unroll
        for (int i = 0; i < 32; ++i) { G1[i] = 0.f; G2[i] = 0.f; G3[i] = 0.f; }
        #pragma unroll
        for (int kt = 0; kt < 4; ++kt) {
            #pragma unroll
            for (int ntp = 0; ntp < 4; ++ntp) {
                uint32_t b4[4];
                LDSM4T(b4, whh_b + kt * (16 * RS) + ntp * 32);
                MMA4(&G1[ntp*8],   &SH[2][kt*4], b4[0], b4[1]); MMA4(&G1[ntp*8+4], &SH[2][kt*4], b4[2], b4[3]);
                MMA4(&G2[ntp*8],   &SH[1][kt*4], b4[0], b4[1]); MMA4(&G2[ntp*8+4], &SH[1][kt*4], b4[2], b4[3]);
                MMA4(&G3[ntp*8],   &SH[0][kt*4], b4[0], b4[1]); MMA4(&G3[ntp*8+4], &SH[0][kt*4], b4[2], b4[3]);
            }
        }

        // ---- epilogue: y from G1; S3new=tanh(A+G2); S2new=tanh(A+G3); S1new=tanh(A) ----
        float p = 0.f, p8 = 0.f;
        #pragma unroll
        for (int j = 0; j < 8; ++j) {
            float2 w2 = *(const float2*)&wop[j * 8 + 2 * c];
            float s0, s1, s2, s3;
            tanh4(A[4*j+0] + G1[4*j+0], A[4*j+1] + G1[4*j+1],
                  A[4*j+2] + G1[4*j+2], A[4*j+3] + G1[4*j+3], s0, s1, s2, s3);
            p  += s0 * w2.x + s1 * w2.y;
            p8 += s2 * w2.x + s3 * w2.y;
        }
        #pragma unroll
        for (int j = 0; j < 8; ++j) {
            float s0, s1, s2, s3;
            tanh4(A[4*j+0] + G2[4*j+0], A[4*j+1] + G2[4*j+1],
                  A[4*j+2] + G2[4*j+2], A[4*j+3] + G2[4*j+3], s0, s1, s2, s3);
            const int kt = j >> 1;
            if ((j & 1) == 0) {
                SH[2][kt*4+0] = packh2(s0, s1);
                SH[2][kt*4+1] = packh2(s2, s3);
            } else {
                SH[2][kt*4+2] = packh2(s0, s1);
                SH[2][kt*4+3] = packh2(s2, s3);
            }
        }
        #pragma unroll
        for (int j = 0; j < 8; ++j) {
            float s0, s1, s2, s3;
            tanh4(A[4*j+0] + G3[4*j+0], A[4*j+1] + G3[4*j+1],
                  A[4*j+2] + G3[4*j+2], A[4*j+3] + G3[4*j+3], s0, s1, s2, s3);
            const int kt = j >> 1;
            if ((j & 1) == 0) {
                SH[1][kt*4+0] = packh2(s0, s1);
                SH[1][kt*4+1] = packh2(s2, s3);
            } else {
                SH[1][kt*4+2] = packh2(s0, s1);
                SH[1][kt*4+3] = packh2(s2, s3);
            }
        }
        #pragma unroll
        for (int j = 0; j < 8; ++j) {
            float s0, s1, s2, s3;
            tanh4(A[4*j+0], A[4*j+1], A[4*j+2], A[4*j+3], s0, s1, s2, s3);
            const int kt = j >> 1;
            if ((j & 1) == 0) {
                SH[0][kt*4+0] = packh2(s0, s1);
                SH[0][kt*4+1] = packh2(s2, s3);
            } else {
                SH[0][kt*4+2] = packh2(s0, s1);
                SH[0][kt*4+3] = packh2(s2, s3);
            }
        }

        // ---- emit y ----
        p  += __shfl_xor_sync(0xffffffffu, p, 1);
        p  += __shfl_xor_sync(0xffffffffu, p, 2);
        p8 += __shfl_xor_sync(0xffffffffu, p8, 1);
        p8 += __shfl_xor_sync(0xffffffffu, p8, 2);
        if (c == 0 && t >= emit_lo) {
            size_t base = (size_t)(t + 1) * NGRID + cell0 + m0;
            out[base + gr]     = p  + bout;
            out[base + gr + 8] = p8 + bout;
        }
    }
}

extern "C" __global__ void narx_zero_head(float* __restrict__ out) {
    int i = blockIdx.x * blockDim.x + threadIdx.x;
    if (i < DLY * NGRID) out[i] = 0.f;
}

extern "C" void kernel_launch(void* const* d_in, const int* in_sizes, int n_in,
                              void* d_out, int out_size) {
    const float* x     = (const float*)d_in[0];
    const float* W_in  = (const float*)d_in[1];
    const float* b_in  = (const float*)d_in[2];
    const float* W_xh  = (const float*)d_in[3];
    const float* W_hh  = (const float*)d_in[4];
    const float* b_h   = (const float*)d_in[5];
    const float* W_out = (const float*)d_in[6];
    const float* b_out = (const float*)d_in[7];
    float* out = (float*)d_out;

    narx_zero_head<<<(DLY * NGRID + 255) / 256, 256>>>(out);

    dim3 grid(NGRID / NG, TCH);
    narx_frag_kernel<<<grid, NTHR>>>(
        x, W_in, b_in, W_xh, W_hh, b_h, W_out, b_out, out);
}

// round 15
// speedup vs baseline: 3.5266x; 1.5369x over previous
#include <cuda_runtime.h>
#include <cuda_fp16.h>
#include <cstdint>

#define NT    512
#define NGRID 2048
#define NXF   16
#define HID   64
#define DLY   4
#define NG    128
#define NTHR  256
#define TCH   9
#define CH    57
#define RS    144        // weight tile row stride (72 fp16)

#define WT    (64 * RS)
#define WIT   (16 * RS)
#define SM_WXH  0
#define SM_WHH  (WT)
#define SM_WIN  (2 * WT)
#define SM_BIN  (2 * WT + WIT)
#define SM_BH   (SM_BIN + 256)
#define SM_WOUT (SM_BH + 256)
#define SM_TOTAL (SM_WOUT + 256)   // ~21.5 KB

__device__ __forceinline__ uint32_t smem_u32(const void* p) {
    uint32_t a;
    asm("{ .reg .u64 t; cvta.to.shared.u64 t, %1; cvt.u32.u64 %0, t; }" : "=r"(a) : "l"(p));
    return a;
}

// no "memory" clobber: smem is read-only after the prologue barrier
#define LDSM4T(r, addr) \
    asm volatile("ldmatrix.sync.aligned.m8n8.x4.trans.shared.b16 {%0,%1,%2,%3}, [%4];" \
        : "=r"((r)[0]), "=r"((r)[1]), "=r"((r)[2]), "=r"((r)[3]) : "r"(addr))
#define MMA4(d, a, b0_, b1_) \
    asm volatile("mma.sync.aligned.m16n8k16.row.col.f32.f16.f16.f32 " \
        "{%0,%1,%2,%3}, {%4,%5,%6,%7}, {%8,%9}, {%0,%1,%2,%3};" \
        : "+f"((d)[0]), "+f"((d)[1]), "+f"((d)[2]), "+f"((d)[3]) \
        : "r"((a)[0]), "r"((a)[1]), "r"((a)[2]), "r"((a)[3]), "r"(b0_), "r"(b1_))

// exact fp32 tanh, 4 values sharing ONE reciprocal (for the y output path)
__device__ __forceinline__ void tanh4(float v0, float v1, float v2, float v3,
                                      float& s0, float& s1, float& s2, float& s3) {
    float d0 = fminf(__expf(2.f * v0) + 1.f, 1e7f);
    float d1 = fminf(__expf(2.f * v1) + 1.f, 1e7f);
    float d2 = fminf(__expf(2.f * v2) + 1.f, 1e7f);
    float d3 = fminf(__expf(2.f * v3) + 1.f, 1e7f);
    float p01 = d0 * d1, p23 = d2 * d3;
    float P = p01 * p23;
    float r;
    asm("rcp.approx.f32 %0, %1;" : "=f"(r) : "f"(P));
    float r01 = r * p23;   // 1/(d0*d1)
    float r23 = r * p01;   // 1/(d2*d3)
    s0 = fmaf(-2.f, d1 * r01, 1.f);
    s1 = fmaf(-2.f, d0 * r01, 1.f);
    s2 = fmaf(-2.f, d3 * r23, 1.f);
    s3 = fmaf(-2.f, d2 * r23, 1.f);
}

__device__ __forceinline__ uint32_t packh2(float a, float b) {
    __half2 h = __floats2half2_rn(a, b);
    return *(uint32_t*)&h;
}
__device__ __forceinline__ uint32_t packl2(float a, float b, uint32_t hi) {
    __half2 h = *(__half2*)&hi;
    float2 f = __half22float2(h);
    __half2 l = __floats2half2_rn(a - f.x, b - f.y);
    return *(uint32_t*)&l;
}
// two fp16 tanh in one MUFU, result already in A-frag half2 layout
__device__ __forceinline__ uint32_t htanh2(uint32_t h) {
    uint32_t t;
    asm("tanh.approx.f16x2 %0, %1;" : "=r"(t) : "r"(h));
    return t;
}

extern "C" __global__ void __launch_bounds__(NTHR, 1)
narx_frag_kernel(const float* __restrict__ x,
                 const float* __restrict__ W_in,  const float* __restrict__ b_in,
                 const float* __restrict__ W_xh,  const float* __restrict__ W_hh,
                 const float* __restrict__ b_h,   const float* __restrict__ W_out,
                 const float* __restrict__ b_out, float* __restrict__ out)
{
    __shared__ __align__(16) char smp[SM_TOTAL];
    const uint32_t sb = smem_u32(smp);
    const int tid = threadIdx.x, wid = tid >> 5, lane = tid & 31;
    const int gr = lane >> 2, c = lane & 3;
    const int m0 = wid * 16;
    const int cell0 = blockIdx.x * NG;
    const int tb = blockIdx.y * CH;
    const int te = min(tb + CH, NT - 1);
    const int ts = max(tb - (DLY - 1), 0);
    const int emit_lo = max(tb, DLY - 1);

    // ---- prologue: fp16-rn weights into smem ----
    for (int i = tid; i < HID * HID; i += NTHR) {
        int k = i >> 6, n = i & 63;
        ((__half*)(smp + SM_WXH))[k*72 + n] = __float2half_rn(W_xh[i]);
        ((__half*)(smp + SM_WHH))[k*72 + n] = __float2half_rn(W_hh[i]);
    }
    for (int i = tid; i < NXF * HID; i += NTHR) {
        int k = i >> 6, n = i & 63;
        ((__half*)(smp + SM_WIN))[k*72 + n] = __float2half_rn(W_in[i]);
    }
    if (tid < HID) {
        ((float*)(smp + SM_BIN))[tid]  = b_in[tid];
        ((float*)(smp + SM_BH))[tid]   = b_h[tid];
        ((float*)(smp + SM_WOUT))[tid] = W_out[tid];
    }
    const float bout = b_out[0];
    __syncthreads();   // smem read-only hereafter

    const uint32_t bOff = (uint32_t)(((lane & 7) + ((lane >> 3) & 1) * 8) * RS + (lane >> 4) * 16);
    const uint32_t wxh_b = sb + SM_WXH + bOff;
    const uint32_t whh_b = sb + SM_WHH + bOff;
    const uint32_t win_b = sb + SM_WIN + bOff;

    const float* binp = (const float*)(smp + SM_BIN);
    const float* bhp  = (const float*)(smp + SM_BH);
    const float* wop  = (const float*)(smp + SM_WOUT);

    // state A-frags in registers: 3 states x (4kt x 4regs), fp16 hi only
    uint32_t SH[3][16];
    #pragma unroll
    for (int r = 0; r < 3; ++r)
        #pragma unroll
        for (int q = 0; q < 16; ++q) SH[r][q] = 0u;

    const size_t tstride = (size_t)NGRID * NXF;
    const float* xr0 = x + ((size_t)ts * NGRID + cell0 + m0 + gr)     * NXF + 2 * c;
    const float* xr8 = x + ((size_t)ts * NGRID + cell0 + m0 + gr + 8) * NXF + 2 * c;
    float2 xn0 = *(const float2*)(xr0);
    float2 xn1 = *(const float2*)(xr0 + 8);
    float2 xn2 = *(const float2*)(xr8);
    float2 xn3 = *(const float2*)(xr8 + 8);
    xr0 += tstride; xr8 += tstride;

    for (int t = ts; t < te; ++t) {
        // ---- x A-frags (hi + residual fp16; x unbounded, keep 2-term) ----
        uint32_t xh[4], xl[4];
        xh[0] = packh2(xn0.x, xn0.y); xl[0] = packl2(xn0.x, xn0.y, xh[0]);
        xh[1] = packh2(xn2.x, xn2.y); xl[1] = packl2(xn2.x, xn2.y, xh[1]);
        xh[2] = packh2(xn1.x, xn1.y); xl[2] = packl2(xn1.x, xn1.y, xh[2]);
        xh[3] = packh2(xn3.x, xn3.y); xl[3] = packl2(xn3.x, xn3.y, xh[3]);
        xn0 = *(const float2*)(xr0);
        xn1 = *(const float2*)(xr0 + 8);
        xn2 = *(const float2*)(xr8);
        xn3 = *(const float2*)(xr8 + 8);
        xr0 += tstride; xr8 += tstride;

        // ---- U = relu(x @ W_in + b_in), K=16, 2-term in x ----
        uint32_t uh[16];
        {
            float acc[32];
            #pragma unroll
            for (int i = 0; i < 32; ++i) acc[i] = 0.f;
            #pragma unroll
            for (int ntp = 0; ntp < 4; ++ntp) {
                uint32_t b4[4];
                LDSM4T(b4, win_b + ntp * 32);
                MMA4(&acc[ntp*8],   xh, b4[0], b4[1]); MMA4(&acc[ntp*8+4], xh, b4[2], b4[3]);
                MMA4(&acc[ntp*8],   xl, b4[0], b4[1]); MMA4(&acc[ntp*8+4], xl, b4[2], b4[3]);
            }
            #pragma unroll
            for (int j = 0; j < 8; ++j) {
                float2 b2 = *(const float2*)&binp[j * 8 + 2 * c];
                float u0 = fmaxf(acc[4*j+0] + b2.x, 0.f);
                float u1 = fmaxf(acc[4*j+1] + b2.y, 0.f);
                float u2 = fmaxf(acc[4*j+2] + b2.x, 0.f);
                float u3 = fmaxf(acc[4*j+3] + b2.y, 0.f);
                const int kt = j >> 1;
                if ((j & 1) == 0) {
                    uh[kt*4+0] = packh2(u0, u1);
                    uh[kt*4+1] = packh2(u2, u3);
                } else {
                    uh[kt*4+2] = packh2(u0, u1);
                    uh[kt*4+3] = packh2(u2, u3);
                }
            }
        }

        // ---- A = U @ Wxh + b_h, K=64 (hi-only U) ----
        float A[32];
        #pragma unroll
        for (int i = 0; i < 32; ++i) A[i] = 0.f;
        #pragma unroll
        for (int kt = 0; kt < 4; ++kt) {
            #pragma unroll
            for (int ntp = 0; ntp < 4; ++ntp) {
                uint32_t b4[4];
                LDSM4T(b4, wxh_b + kt * (16 * RS) + ntp * 32);
                MMA4(&A[ntp*8],   &uh[kt*4], b4[0], b4[1]); MMA4(&A[ntp*8+4], &uh[kt*4], b4[2], b4[3]);
            }
        }
        #pragma unroll
        for (int j = 0; j < 8; ++j) {
            float2 b2 = *(const float2*)&bhp[j * 8 + 2 * c];
            A[4*j+0] += b2.x; A[4*j+1] += b2.y; A[4*j+2] += b2.x; A[4*j+3] += b2.y;
        }

        // ---- FUSED state GEMMs (hi-only): G1=S3old@W, G2=S2old@W, G3=S1old@W ----
        float G1[32], G2[32], G3[32];
        #pragma unroll
        for (int i = 0; i < 32; ++i) { G1[i] = 0.f; G2[i] = 0.f; G3[i] = 0.f; }
        #pragma unroll
        for (int kt = 0; kt < 4; ++kt) {
            #pragma unroll
            for (int ntp = 0; ntp < 4; ++ntp) {
                uint32_t b4[4];
                LDSM4T(b4, whh_b + kt * (16 * RS) + ntp * 32);
                MMA4(&G1[ntp*8],   &SH[2][kt*4], b4[0], b4[1]); MMA4(&G1[ntp*8+4], &SH[2][kt*4], b4[2], b4[3]);
                MMA4(&G2[ntp*8],   &SH[1][kt*4], b4[0], b4[1]); MMA4(&G2[ntp*8+4], &SH[1][kt*4], b4[2], b4[3]);
                MMA4(&G3[ntp*8],   &SH[0][kt*4], b4[0], b4[1]); MMA4(&G3[ntp*8+4], &SH[0][kt*4], b4[2], b4[3]);
            }
        }

        // ---- epilogue ----
        // y from G1: exact fp32 tanh (feeds output directly)
        float p = 0.f, p8 = 0.f;
        #pragma unroll
        for (int j = 0; j < 8; ++j) {
            float2 w2 = *(const float2*)&wop[j * 8 + 2 * c];
            float s0, s1, s2, s3;
            tanh4(A[4*j+0] + G1[4*j+0], A[4*j+1] + G1[4*j+1],
                  A[4*j+2] + G1[4*j+2], A[4*j+3] + G1[4*j+3], s0, s1, s2, s3);
            p  += s0 * w2.x + s1 * w2.y;
            p8 += s2 * w2.x + s3 * w2.y;
        }
        // S3new = tanh(A + G2)  — fp16 hardware tanh, result already packed
        #pragma unroll
        for (int j = 0; j < 8; ++j) {
            uint32_t t01 = htanh2(packh2(A[4*j+0] + G2[4*j+0], A[4*j+1] + G2[4*j+1]));
            uint32_t t23 = htanh2(packh2(A[4*j+2] + G2[4*j+2], A[4*j+3] + G2[4*j+3]));
            const int kt = j >> 1;
            if ((j & 1) == 0) { SH[2][kt*4+0] = t01; SH[2][kt*4+1] = t23; }
            else              { SH[2][kt*4+2] = t01; SH[2][kt*4+3] = t23; }
        }
        // S2new = tanh(A + G3)
        #pragma unroll
        for (int j = 0; j < 8; ++j) {
            uint32_t t01 = htanh2(packh2(A[4*j+0] + G3[4*j+0], A[4*j+1] + G3[4*j+1]));
            uint32_t t23 = htanh2(packh2(A[4*j+2] + G3[4*j+2], A[4*j+3] + G3[4*j+3]));
            const int kt = j >> 1;
            if ((j & 1) == 0) { SH[1][kt*4+0] = t01; SH[1][kt*4+1] = t23; }
            else              { SH[1][kt*4+2] = t01; SH[1][kt*4+3] = t23; }
        }
        // S1new = tanh(A)
        #pragma unroll
        for (int j = 0; j < 8; ++j) {
            uint32_t t01 = htanh2(packh2(A[4*j+0], A[4*j+1]));
            uint32_t t23 = htanh2(packh2(A[4*j+2], A[4*j+3]));
            const int kt = j >> 1;
            if ((j & 1) == 0) { SH[0][kt*4+0] = t01; SH[0][kt*4+1] = t23; }
            else              { SH[0][kt*4+2] = t01; SH[0][kt*4+3] = t23; }
        }

        // ---- emit y ----
        p  += __shfl_xor_sync(0xffffffffu, p, 1);
        p  += __shfl_xor_sync(0xffffffffu, p, 2);
        p8 += __shfl_xor_sync(0xffffffffu, p8, 1);
        p8 += __shfl_xor_sync(0xffffffffu, p8, 2);
        if (c == 0 && t >= emit_lo) {
            size_t base = (size_t)(t + 1) * NGRID + cell0 + m0;
            out[base + gr]     = p  + bout;
            out[base + gr + 8] = p8 + bout;
        }
    }
}

extern "C" __global__ void narx_zero_head(float* __restrict__ out) {
    int i = blockIdx.x * blockDim.x + threadIdx.x;
    if (i < DLY * NGRID) out[i] = 0.f;
}

extern "C" void kernel_launch(void* const* d_in, const int* in_sizes, int n_in,
                              void* d_out, int out_size) {
    const float* x     = (const float*)d_in[0];
    const float* W_in  = (const float*)d_in[1];
    const float* b_in  = (const float*)d_in[2];
    const float* W_xh  = (const float*)d_in[3];
    const float* W_hh  = (const float*)d_in[4];
    const float* b_h   = (const float*)d_in[5];
    const float* W_out = (const float*)d_in[6];
    const float* b_out = (const float*)d_in[7];
    float* out = (float*)d_out;

    narx_zero_head<<<(DLY * NGRID + 255) / 256, 256>>>(out);

    dim3 grid(NGRID / NG, TCH);
    narx_frag_kernel<<<grid, NTHR>>>(
        x, W_in, b_in, W_xh, W_hh, b_h, W_out, b_out, out);
}

// round 16
// speedup vs baseline: 4.3078x; 1.2215x over previous
#include <cuda_runtime.h>
#include <cuda_fp16.h>
#include <cstdint>

#define NT    512
#define NGRID 2048
#define NXF   16
#define HID   64
#define DLY   4
#define NG    128
#define NTHR  256
#define TCH   9
#define CH    57
#define RS    144        // weight tile row stride (72 fp16)

#define WT    (64 * RS)
#define WIT   (16 * RS)
#define SM_WXH  0
#define SM_WHH  (WT)
#define SM_WIN  (2 * WT)
#define SM_BIN  (2 * WT + WIT)
#define SM_BH   (SM_BIN + 256)
#define SM_WOUT (SM_BH + 256)
#define SM_TOTAL (SM_WOUT + 256)   // ~21.5 KB

__device__ __forceinline__ uint32_t smem_u32(const void* p) {
    uint32_t a;
    asm("{ .reg .u64 t; cvta.to.shared.u64 t, %1; cvt.u32.u64 %0, t; }" : "=r"(a) : "l"(p));
    return a;
}

// no "memory" clobber: smem is read-only after the prologue barrier
#define LDSM4T(r, addr) \
    asm volatile("ldmatrix.sync.aligned.m8n8.x4.trans.shared.b16 {%0,%1,%2,%3}, [%4];" \
        : "=r"((r)[0]), "=r"((r)[1]), "=r"((r)[2]), "=r"((r)[3]) : "r"(addr))
#define MMA4(d, a, b0_, b1_) \
    asm volatile("mma.sync.aligned.m16n8k16.row.col.f32.f16.f16.f32 " \
        "{%0,%1,%2,%3}, {%4,%5,%6,%7}, {%8,%9}, {%0,%1,%2,%3};" \
        : "+f"((d)[0]), "+f"((d)[1]), "+f"((d)[2]), "+f"((d)[3]) \
        : "r"((a)[0]), "r"((a)[1]), "r"((a)[2]), "r"((a)[3]), "r"(b0_), "r"(b1_))

__device__ __forceinline__ uint32_t packh2(float a, float b) {
    __half2 h = __floats2half2_rn(a, b);
    return *(uint32_t*)&h;
}
__device__ __forceinline__ uint32_t packl2(float a, float b, uint32_t hi) {
    __half2 h = *(__half2*)&hi;
    float2 f = __half22float2(h);
    __half2 l = __floats2half2_rn(a - f.x, b - f.y);
    return *(uint32_t*)&l;
}
// two fp16 tanh in one MUFU, result already in A-frag half2 layout
__device__ __forceinline__ uint32_t htanh2(uint32_t h) {
    uint32_t t;
    asm("tanh.approx.f16x2 %0, %1;" : "=r"(t) : "r"(h));
    return t;
}
// half2 add on packed u32
__device__ __forceinline__ uint32_t hadd2u(uint32_t a, uint32_t b) {
    __half2 r = __hadd2(*(__half2*)&a, *(__half2*)&b);
    return *(uint32_t*)&r;
}
// fp32 hardware tanh (1 MUFU, rel err ~2^-11) for the y path
__device__ __forceinline__ float tanh32(float v) {
    float t;
    asm("tanh.approx.f32 %0, %1;" : "=f"(t) : "f"(v));
    return t;
}

extern "C" __global__ void __launch_bounds__(NTHR, 1)
narx_frag_kernel(const float* __restrict__ x,
                 const float* __restrict__ W_in,  const float* __restrict__ b_in,
                 const float* __restrict__ W_xh,  const float* __restrict__ W_hh,
                 const float* __restrict__ b_h,   const float* __restrict__ W_out,
                 const float* __restrict__ b_out, float* __restrict__ out)
{
    __shared__ __align__(16) char smp[SM_TOTAL];
    const uint32_t sb = smem_u32(smp);
    const int tid = threadIdx.x, wid = tid >> 5, lane = tid & 31;
    const int gr = lane >> 2, c = lane & 3;
    const int m0 = wid * 16;
    const int cell0 = blockIdx.x * NG;
    const int tb = blockIdx.y * CH;
    const int te = min(tb + CH, NT - 1);
    const int ts = max(tb - (DLY - 1), 0);
    const int emit_lo = max(tb, DLY - 1);

    // ---- prologue: fp16-rn weights into smem ----
    for (int i = tid; i < HID * HID; i += NTHR) {
        int k = i >> 6, n = i & 63;
        ((__half*)(smp + SM_WXH))[k*72 + n] = __float2half_rn(W_xh[i]);
        ((__half*)(smp + SM_WHH))[k*72 + n] = __float2half_rn(W_hh[i]);
    }
    for (int i = tid; i < NXF * HID; i += NTHR) {
        int k = i >> 6, n = i & 63;
        ((__half*)(smp + SM_WIN))[k*72 + n] = __float2half_rn(W_in[i]);
    }
    if (tid < HID) {
        ((float*)(smp + SM_BIN))[tid]  = b_in[tid];
        ((float*)(smp + SM_BH))[tid]   = b_h[tid];
        ((float*)(smp + SM_WOUT))[tid] = W_out[tid];
    }
    const float bout = b_out[0];
    __syncthreads();   // smem read-only hereafter

    const uint32_t bOff = (uint32_t)(((lane & 7) + ((lane >> 3) & 1) * 8) * RS + (lane >> 4) * 16);
    const uint32_t wxh_b = sb + SM_WXH + bOff;
    const uint32_t whh_b = sb + SM_WHH + bOff;
    const uint32_t win_b = sb + SM_WIN + bOff;

    const float* binp = (const float*)(smp + SM_BIN);
    const float* bhp  = (const float*)(smp + SM_BH);
    const float* wop  = (const float*)(smp + SM_WOUT);

    // state A-frags in registers: 3 states x (4kt x 4regs), fp16 hi only
    uint32_t SH[3][16];
    #pragma unroll
    for (int r = 0; r < 3; ++r)
        #pragma unroll
        for (int q = 0; q < 16; ++q) SH[r][q] = 0u;

    const size_t tstride = (size_t)NGRID * NXF;
    const float* xr0 = x + ((size_t)ts * NGRID + cell0 + m0 + gr)     * NXF + 2 * c;
    const float* xr8 = x + ((size_t)ts * NGRID + cell0 + m0 + gr + 8) * NXF + 2 * c;
    float2 xn0 = *(const float2*)(xr0);
    float2 xn1 = *(const float2*)(xr0 + 8);
    float2 xn2 = *(const float2*)(xr8);
    float2 xn3 = *(const float2*)(xr8 + 8);
    xr0 += tstride; xr8 += tstride;

    for (int t = ts; t < te; ++t) {
        // ---- x A-frags (hi + residual fp16; x unbounded, keep 2-term) ----
        uint32_t xh[4], xl[4];
        xh[0] = packh2(xn0.x, xn0.y); xl[0] = packl2(xn0.x, xn0.y, xh[0]);
        xh[1] = packh2(xn2.x, xn2.y); xl[1] = packl2(xn2.x, xn2.y, xh[1]);
        xh[2] = packh2(xn1.x, xn1.y); xl[2] = packl2(xn1.x, xn1.y, xh[2]);
        xh[3] = packh2(xn3.x, xn3.y); xl[3] = packl2(xn3.x, xn3.y, xh[3]);
        xn0 = *(const float2*)(xr0);
        xn1 = *(const float2*)(xr0 + 8);
        xn2 = *(const float2*)(xr8);
        xn3 = *(const float2*)(xr8 + 8);
        xr0 += tstride; xr8 += tstride;

        // ---- U = relu(x @ W_in + b_in), K=16, 2-term in x ----
        uint32_t uh[16];
        {
            float acc[32];
            #pragma unroll
            for (int i = 0; i < 32; ++i) acc[i] = 0.f;
            #pragma unroll
            for (int ntp = 0; ntp < 4; ++ntp) {
                uint32_t b4[4];
                LDSM4T(b4, win_b + ntp * 32);
                MMA4(&acc[ntp*8],   xh, b4[0], b4[1]); MMA4(&acc[ntp*8+4], xh, b4[2], b4[3]);
                MMA4(&acc[ntp*8],   xl, b4[0], b4[1]); MMA4(&acc[ntp*8+4], xl, b4[2], b4[3]);
            }
            #pragma unroll
            for (int j = 0; j < 8; ++j) {
                float2 b2 = *(const float2*)&binp[j * 8 + 2 * c];
                float u0 = fmaxf(acc[4*j+0] + b2.x, 0.f);
                float u1 = fmaxf(acc[4*j+1] + b2.y, 0.f);
                float u2 = fmaxf(acc[4*j+2] + b2.x, 0.f);
                float u3 = fmaxf(acc[4*j+3] + b2.y, 0.f);
                const int kt = j >> 1;
                if ((j & 1) == 0) {
                    uh[kt*4+0] = packh2(u0, u1);
                    uh[kt*4+1] = packh2(u2, u3);
                } else {
                    uh[kt*4+2] = packh2(u0, u1);
                    uh[kt*4+3] = packh2(u2, u3);
                }
            }
        }

        // ---- A = U @ Wxh + b_h, K=64 (hi-only U) ----
        float A[32];
        #pragma unroll
        for (int i = 0; i < 32; ++i) A[i] = 0.f;
        #pragma unroll
        for (int kt = 0; kt < 4; ++kt) {
            #pragma unroll
            for (int ntp = 0; ntp < 4; ++ntp) {
                uint32_t b4[4];
                LDSM4T(b4, wxh_b + kt * (16 * RS) + ntp * 32);
                MMA4(&A[ntp*8],   &uh[kt*4], b4[0], b4[1]); MMA4(&A[ntp*8+4], &uh[kt*4], b4[2], b4[3]);
            }
        }
        #pragma unroll
        for (int j = 0; j < 8; ++j) {
            float2 b2 = *(const float2*)&bhp[j * 8 + 2 * c];
            A[4*j+0] += b2.x; A[4*j+1] += b2.y; A[4*j+2] += b2.x; A[4*j+3] += b2.y;
        }

        // ---- FUSED state GEMMs (hi-only): G1=S3old@W, G2=S2old@W, G3=S1old@W ----
        float G1[32], G2[32], G3[32];
        #pragma unroll
        for (int i = 0; i < 32; ++i) { G1[i] = 0.f; G2[i] = 0.f; G3[i] = 0.f; }
        #pragma unroll
        for (int kt = 0; kt < 4; ++kt) {
            #pragma unroll
            for (int ntp = 0; ntp < 4; ++ntp) {
                uint32_t b4[4];
                LDSM4T(b4, whh_b + kt * (16 * RS) + ntp * 32);
                MMA4(&G1[ntp*8],   &SH[2][kt*4], b4[0], b4[1]); MMA4(&G1[ntp*8+4], &SH[2][kt*4], b4[2], b4[3]);
                MMA4(&G2[ntp*8],   &SH[1][kt*4], b4[0], b4[1]); MMA4(&G2[ntp*8+4], &SH[1][kt*4], b4[2], b4[3]);
                MMA4(&G3[ntp*8],   &SH[0][kt*4], b4[0], b4[1]); MMA4(&G3[ntp*8+4], &SH[0][kt*4], b4[2], b4[3]);
            }
        }

        // ---- epilogue ----
        // y from G1: fp32 hardware tanh (feeds output directly)
        float p = 0.f, p8 = 0.f;
        #pragma unroll
        for (int j = 0; j < 8; ++j) {
            float2 w2 = *(const float2*)&wop[j * 8 + 2 * c];
            p  += tanh32(A[4*j+0] + G1[4*j+0]) * w2.x
                + tanh32(A[4*j+1] + G1[4*j+1]) * w2.y;
            p8 += tanh32(A[4*j+2] + G1[4*j+2]) * w2.x
                + tanh32(A[4*j+3] + G1[4*j+3]) * w2.y;
        }
        // pack A once into half2 A-frag layout
        uint32_t ah01[8], ah23[8];
        #pragma unroll
        for (int j = 0; j < 8; ++j) {
            ah01[j] = packh2(A[4*j+0], A[4*j+1]);
            ah23[j] = packh2(A[4*j+2], A[4*j+3]);
        }
        // S3new = tanh(A + G2): half2 adds + fp16 hardware tanh
        #pragma unroll
        for (int j = 0; j < 8; ++j) {
            uint32_t t01 = htanh2(hadd2u(ah01[j], packh2(G2[4*j+0], G2[4*j+1])));
            uint32_t t23 = htanh2(hadd2u(ah23[j], packh2(G2[4*j+2], G2[4*j+3])));
            const int kt = j >> 1;
            if ((j & 1) == 0) { SH[2][kt*4+0] = t01; SH[2][kt*4+1] = t23; }
            else              { SH[2][kt*4+2] = t01; SH[2][kt*4+3] = t23; }
        }
        // S2new = tanh(A + G3)
        #pragma unroll
        for (int j = 0; j < 8; ++j) {
            uint32_t t01 = htanh2(hadd2u(ah01[j], packh2(G3[4*j+0], G3[4*j+1])));
            uint32_t t23 = htanh2(hadd2u(ah23[j], packh2(G3[4*j+2], G3[4*j+3])));
            const int kt = j >> 1;
            if ((j & 1) == 0) { SH[1][kt*4+0] = t01; SH[1][kt*4+1] = t23; }
            else              { SH[1][kt*4+2] = t01; SH[1][kt*4+3] = t23; }
        }
        // S1new = tanh(A): directly from packed A
        #pragma unroll
        for (int j = 0; j < 8; ++j) {
            uint32_t t01 = htanh2(ah01[j]);
            uint32_t t23 = htanh2(ah23[j]);
            const int kt = j >> 1;
            if ((j & 1) == 0) { SH[0][kt*4+0] = t01; SH[0][kt*4+1] = t23; }
            else              { SH[0][kt*4+2] = t01; SH[0][kt*4+3] = t23; }
        }

        // ---- emit y ----
        p  += __shfl_xor_sync(0xffffffffu, p, 1);
        p  += __shfl_xor_sync(0xffffffffu, p, 2);
        p8 += __shfl_xor_sync(0xffffffffu, p8, 1);
        p8 += __shfl_xor_sync(0xffffffffu, p8, 2);
        if (c == 0 && t >= emit_lo) {
            size_t base = (size_t)(t + 1) * NGRID + cell0 + m0;
            out[base + gr]     = p  + bout;
            out[base + gr + 8] = p8 + bout;
        }
    }
}

extern "C" __global__ void narx_zero_head(float* __restrict__ out) {
    int i = blockIdx.x * blockDim.x + threadIdx.x;
    if (i < DLY * NGRID) out[i] = 0.f;
}

extern "C" void kernel_launch(void* const* d_in, const int* in_sizes, int n_in,
                              void* d_out, int out_size) {
    const float* x     = (const float*)d_in[0];
    const float* W_in  = (const float*)d_in[1];
    const float* b_in  = (const float*)d_in[2];
    const float* W_xh  = (const float*)d_in[3];
    const float* W_hh  = (const float*)d_in[4];
    const float* b_h   = (const float*)d_in[5];
    const float* W_out = (const float*)d_in[6];
    const float* b_out = (const float*)d_in[7];
    float* out = (float*)d_out;

    narx_zero_head<<<(DLY * NGRID + 255) / 256, 256>>>(out);

    dim3 grid(NGRID / NG, TCH);
    narx_frag_kernel<<<grid, NTHR>>>(
        x, W_in, b_in, W_xh, W_hh, b_h, W_out, b_out, out);
}

// round 17
// speedup vs baseline: 4.3089x; 1.0003x over previous
#include <cuda_runtime.h>
#include <cuda_fp16.h>
#include <cstdint>

#define NT    512
#define NGRID 2048
#define NXF   16
#define HID   64
#define DLY   4
#define NG    128
#define NTHR  256
#define TCH   9
#define CH    57
#define RS    144        // weight tile row stride (72 fp16)

#define WT    (64 * RS)
#define WIT   (16 * RS)
#define SM_WXH  0
#define SM_WHH  (WT)
#define SM_WIN  (2 * WT)
#define SM_BIN  (2 * WT + WIT)
#define SM_BH   (SM_BIN + 256)
#define SM_WOUT (SM_BH + 256)
#define SM_TOTAL (SM_WOUT + 256)   // ~21.5 KB

__device__ __forceinline__ uint32_t smem_u32(const void* p) {
    uint32_t a;
    asm("{ .reg .u64 t; cvta.to.shared.u64 t, %1; cvt.u32.u64 %0, t; }" : "=r"(a) : "l"(p));
    return a;
}

// no "memory" clobber: smem is read-only after the prologue barrier
#define LDSM4T(r, addr) \
    asm volatile("ldmatrix.sync.aligned.m8n8.x4.trans.shared.b16 {%0,%1,%2,%3}, [%4];" \
        : "=r"((r)[0]), "=r"((r)[1]), "=r"((r)[2]), "=r"((r)[3]) : "r"(addr))
#define MMA4(d, a, b0_, b1_) \
    asm volatile("mma.sync.aligned.m16n8k16.row.col.f32.f16.f16.f32 " \
        "{%0,%1,%2,%3}, {%4,%5,%6,%7}, {%8,%9}, {%0,%1,%2,%3};" \
        : "+f"((d)[0]), "+f"((d)[1]), "+f"((d)[2]), "+f"((d)[3]) \
        : "r"((a)[0]), "r"((a)[1]), "r"((a)[2]), "r"((a)[3]), "r"(b0_), "r"(b1_))

__device__ __forceinline__ uint32_t packh2(float a, float b) {
    __half2 h = __floats2half2_rn(a, b);
    return *(uint32_t*)&h;
}
__device__ __forceinline__ uint32_t packl2(float a, float b, uint32_t hi) {
    __half2 h = *(__half2*)&hi;
    float2 f = __half22float2(h);
    __half2 l = __floats2half2_rn(a - f.x, b - f.y);
    return *(uint32_t*)&l;
}
// two fp16 tanh in one MUFU, result already in A-frag half2 layout
__device__ __forceinline__ uint32_t htanh2(uint32_t h) {
    uint32_t t;
    asm("tanh.approx.f16x2 %0, %1;" : "=r"(t) : "r"(h));
    return t;
}
// fp32 hardware tanh (1 MUFU, rel err ~2^-11) for the y path
__device__ __forceinline__ float tanh32(float v) {
    float t;
    asm("tanh.approx.f32 %0, %1;" : "=f"(t) : "f"(v));
    return t;
}

extern "C" __global__ void __launch_bounds__(NTHR, 1)
narx_frag_kernel(const float* __restrict__ x,
                 const float* __restrict__ W_in,  const float* __restrict__ b_in,
                 const float* __restrict__ W_xh,  const float* __restrict__ W_hh,
                 const float* __restrict__ b_h,   const float* __restrict__ W_out,
                 const float* __restrict__ b_out, float* __restrict__ out)
{
    __shared__ __align__(16) char smp[SM_TOTAL];
    const uint32_t sb = smem_u32(smp);
    const int tid = threadIdx.x, wid = tid >> 5, lane = tid & 31;
    const int gr = lane >> 2, c = lane & 3;
    const int m0 = wid * 16;
    const int cell0 = blockIdx.x * NG;
    const int tb = blockIdx.y * CH;
    const int te = min(tb + CH, NT - 1);
    const int ts = max(tb - (DLY - 1), 0);
    const int emit_lo = max(tb, DLY - 1);

    // ---- prologue: fp16-rn weights into smem ----
    for (int i = tid; i < HID * HID; i += NTHR) {
        int k = i >> 6, n = i & 63;
        ((__half*)(smp + SM_WXH))[k*72 + n] = __float2half_rn(W_xh[i]);
        ((__half*)(smp + SM_WHH))[k*72 + n] = __float2half_rn(W_hh[i]);
    }
    for (int i = tid; i < NXF * HID; i += NTHR) {
        int k = i >> 6, n = i & 63;
        ((__half*)(smp + SM_WIN))[k*72 + n] = __float2half_rn(W_in[i]);
    }
    if (tid < HID) {
        ((float*)(smp + SM_BIN))[tid]  = b_in[tid];
        ((float*)(smp + SM_BH))[tid]   = b_h[tid];
        ((float*)(smp + SM_WOUT))[tid] = W_out[tid];
    }
    const float bout = b_out[0];
    __syncthreads();   // smem read-only hereafter

    const uint32_t bOff = (uint32_t)(((lane & 7) + ((lane >> 3) & 1) * 8) * RS + (lane >> 4) * 16);
    const uint32_t wxh_b = sb + SM_WXH + bOff;
    const uint32_t whh_b = sb + SM_WHH + bOff;
    const uint32_t win_b = sb + SM_WIN + bOff;

    const float* binp = (const float*)(smp + SM_BIN);
    const float* bhp  = (const float*)(smp + SM_BH);
    const float* wop  = (const float*)(smp + SM_WOUT);

    // biases for this lane's columns, loaded once (loop-invariant)
    float bin_r[16], bh_r[16];
    #pragma unroll
    for (int j = 0; j < 8; ++j) {
        float2 b2 = *(const float2*)&binp[j * 8 + 2 * c];
        bin_r[2*j] = b2.x; bin_r[2*j+1] = b2.y;
        float2 h2 = *(const float2*)&bhp[j * 8 + 2 * c];
        bh_r[2*j] = h2.x; bh_r[2*j+1] = h2.y;
    }

    // state A-frags in registers: 3 states x (4kt x 4regs), fp16 hi only
    uint32_t SH[3][16];
    #pragma unroll
    for (int r = 0; r < 3; ++r)
        #pragma unroll
        for (int q = 0; q < 16; ++q) SH[r][q] = 0u;

    const size_t tstride = (size_t)NGRID * NXF;
    const float* xr0 = x + ((size_t)ts * NGRID + cell0 + m0 + gr)     * NXF + 2 * c;
    const float* xr8 = x + ((size_t)ts * NGRID + cell0 + m0 + gr + 8) * NXF + 2 * c;
    float2 xn0 = *(const float2*)(xr0);
    float2 xn1 = *(const float2*)(xr0 + 8);
    float2 xn2 = *(const float2*)(xr8);
    float2 xn3 = *(const float2*)(xr8 + 8);
    xr0 += tstride; xr8 += tstride;

    for (int t = ts; t < te; ++t) {
        // ---- x A-frags (hi + residual fp16; x unbounded, keep 2-term) ----
        uint32_t xh[4], xl[4];
        xh[0] = packh2(xn0.x, xn0.y); xl[0] = packl2(xn0.x, xn0.y, xh[0]);
        xh[1] = packh2(xn2.x, xn2.y); xl[1] = packl2(xn2.x, xn2.y, xh[1]);
        xh[2] = packh2(xn1.x, xn1.y); xl[2] = packl2(xn1.x, xn1.y, xh[2]);
        xh[3] = packh2(xn3.x, xn3.y); xl[3] = packl2(xn3.x, xn3.y, xh[3]);
        xn0 = *(const float2*)(xr0);
        xn1 = *(const float2*)(xr0 + 8);
        xn2 = *(const float2*)(xr8);
        xn3 = *(const float2*)(xr8 + 8);
        xr0 += tstride; xr8 += tstride;

        // ---- U = relu(x @ W_in + b_in), K=16, 2-term in x; acc seeded b_in ----
        uint32_t uh[16];
        {
            float acc[32];
            #pragma unroll
            for (int j = 0; j < 8; ++j) {
                acc[4*j+0] = bin_r[2*j];   acc[4*j+1] = bin_r[2*j+1];
                acc[4*j+2] = bin_r[2*j];   acc[4*j+3] = bin_r[2*j+1];
            }
            #pragma unroll
            for (int ntp = 0; ntp < 4; ++ntp) {
                uint32_t b4[4];
                LDSM4T(b4, win_b + ntp * 32);
                MMA4(&acc[ntp*8],   xh, b4[0], b4[1]); MMA4(&acc[ntp*8+4], xh, b4[2], b4[3]);
                MMA4(&acc[ntp*8],   xl, b4[0], b4[1]); MMA4(&acc[ntp*8+4], xl, b4[2], b4[3]);
            }
            #pragma unroll
            for (int j = 0; j < 8; ++j) {
                const int kt = j >> 1;
                uint32_t p01 = packh2(fmaxf(acc[4*j+0], 0.f), fmaxf(acc[4*j+1], 0.f));
                uint32_t p23 = packh2(fmaxf(acc[4*j+2], 0.f), fmaxf(acc[4*j+3], 0.f));
                if ((j & 1) == 0) { uh[kt*4+0] = p01; uh[kt*4+1] = p23; }
                else              { uh[kt*4+2] = p01; uh[kt*4+3] = p23; }
            }
        }

        // ---- A = U @ Wxh + b_h, K=64 (hi-only U); acc seeded b_h ----
        float A[32];
        #pragma unroll
        for (int j = 0; j < 8; ++j) {
            A[4*j+0] = bh_r[2*j];   A[4*j+1] = bh_r[2*j+1];
            A[4*j+2] = bh_r[2*j];   A[4*j+3] = bh_r[2*j+1];
        }
        #pragma unroll
        for (int kt = 0; kt < 4; ++kt) {
            #pragma unroll
            for (int ntp = 0; ntp < 4; ++ntp) {
                uint32_t b4[4];
                LDSM4T(b4, wxh_b + kt * (16 * RS) + ntp * 32);
                MMA4(&A[ntp*8],   &uh[kt*4], b4[0], b4[1]); MMA4(&A[ntp*8+4], &uh[kt*4], b4[2], b4[3]);
            }
        }

        // ---- FUSED state GEMMs seeded with A:
        //      G1 = A + S3old@W (-> y), G2 = A + S2old@W (-> S3new), G3 = A + S1old@W (-> S2new)
        float G1[32], G2[32], G3[32];
        #pragma unroll
        for (int i = 0; i < 32; ++i) { G1[i] = A[i]; G2[i] = A[i]; G3[i] = A[i]; }
        #pragma unroll
        for (int kt = 0; kt < 4; ++kt) {
            #pragma unroll
            for (int ntp = 0; ntp < 4; ++ntp) {
                uint32_t b4[4];
                LDSM4T(b4, whh_b + kt * (16 * RS) + ntp * 32);
                MMA4(&G1[ntp*8],   &SH[2][kt*4], b4[0], b4[1]); MMA4(&G1[ntp*8+4], &SH[2][kt*4], b4[2], b4[3]);
                MMA4(&G2[ntp*8],   &SH[1][kt*4], b4[0], b4[1]); MMA4(&G2[ntp*8+4], &SH[1][kt*4], b4[2], b4[3]);
                MMA4(&G3[ntp*8],   &SH[0][kt*4], b4[0], b4[1]); MMA4(&G3[ntp*8+4], &SH[0][kt*4], b4[2], b4[3]);
            }
        }

        // ---- epilogue (biases already inside G/A) ----
        // y = sum tanh32(G1) * wout
        float p = 0.f, p8 = 0.f;
        #pragma unroll
        for (int j = 0; j < 8; ++j) {
            float2 w2 = *(const float2*)&wop[j * 8 + 2 * c];
            p  += tanh32(G1[4*j+0]) * w2.x + tanh32(G1[4*j+1]) * w2.y;
            p8 += tanh32(G1[4*j+2]) * w2.x + tanh32(G1[4*j+3]) * w2.y;
        }
        // S3new = tanh(G2), S2new = tanh(G3), S1new = tanh(A) — fp16 hw tanh
        #pragma unroll
        for (int j = 0; j < 8; ++j) {
            const int kt = j >> 1;
            uint32_t t01 = htanh2(packh2(G2[4*j+0], G2[4*j+1]));
            uint32_t t23 = htanh2(packh2(G2[4*j+2], G2[4*j+3]));
            if ((j & 1) == 0) { SH[2][kt*4+0] = t01; SH[2][kt*4+1] = t23; }
            else              { SH[2][kt*4+2] = t01; SH[2][kt*4+3] = t23; }
        }
        #pragma unroll
        for (int j = 0; j < 8; ++j) {
            const int kt = j >> 1;
            uint32_t t01 = htanh2(packh2(G3[4*j+0], G3[4*j+1]));
            uint32_t t23 = htanh2(packh2(G3[4*j+2], G3[4*j+3]));
            if ((j & 1) == 0) { SH[1][kt*4+0] = t01; SH[1][kt*4+1] = t23; }
            else              { SH[1][kt*4+2] = t01; SH[1][kt*4+3] = t23; }
        }
        #pragma unroll
        for (int j = 0; j < 8; ++j) {
            const int kt = j >> 1;
            uint32_t t01 = htanh2(packh2(A[4*j+0], A[4*j+1]));
            uint32_t t23 = htanh2(packh2(A[4*j+2], A[4*j+3]));
            if ((j & 1) == 0) { SH[0][kt*4+0] = t01; SH[0][kt*4+1] = t23; }
            else              { SH[0][kt*4+2] = t01; SH[0][kt*4+3] = t23; }
        }

        // ---- emit y ----
        p  += __shfl_xor_sync(0xffffffffu, p, 1);
        p  += __shfl_xor_sync(0xffffffffu, p, 2);
        p8 += __shfl_xor_sync(0xffffffffu, p8, 1);
        p8 += __shfl_xor_sync(0xffffffffu, p8, 2);
        if (c == 0 && t >= emit_lo) {
            size_t base = (size_t)(t + 1) * NGRID + cell0 + m0;
            out[base + gr]     = p  + bout;
            out[base + gr + 8] = p8 + bout;
        }
    }
}

extern "C" __global__ void narx_zero_head(float* __restrict__ out) {
    int i = blockIdx.x * blockDim.x + threadIdx.x;
    if (i < DLY * NGRID) out[i] = 0.f;
}

extern "C" void kernel_launch(void* const* d_in, const int* in_sizes, int n_in,
                              void* d_out, int out_size) {
    const float* x     = (const float*)d_in[0];
    const float* W_in  = (const float*)d_in[1];
    const float* b_in  = (const float*)d_in[2];
    const float* W_xh  = (const float*)d_in[3];
    const float* W_hh  = (const float*)d_in[4];
    const float* b_h   = (const float*)d_in[5];
    const float* W_out = (const float*)d_in[6];
    const float* b_out = (const float*)d_in[7];
    float* out = (float*)d_out;

    narx_zero_head<<<(DLY * NGRID + 255) / 256, 256>>>(out);

    dim3 grid(NGRID / NG, TCH);
    narx_frag_kernel<<<grid, NTHR>>>(
        x, W_in, b_in, W_xh, W_hh, b_h, W_out, b_out, out);
}